// round 3
// baseline (speedup 1.0000x reference)
#include <cuda_runtime.h>
#include <cstdint>
#include <math.h>

// ---------------- problem constants ----------------
#define B      256
#define T      168
#define F_IN   128
#define H      512
#define H4     2048      // 4*H (encoder gates per direction)
#define KENC   640       // F_IN + H
#define H2     1024      // decoder hidden (2H)
#define NDEC   4096      // 4 * H2
#define KDEC   1024
#define L_OUT  48

// ---------------- GEMM tiling ----------------
#define BM   64
#define BN   128
#define KC   32
#define PAD  36          // smem row stride (floats): 4g+tg distinct banks
#define GSP  129         // gate smem row stride
#define SMTOT 8256       // max(BM*PAD + BN*PAD = 6912, BM*GSP = 8256)

// ---------------- device scratch (static, allowed) ----------------
__device__ float g_xT[(size_t)T * B * F_IN];          // 22 MB, [t][b][f]
__device__ float g_Wenc[2][H4 * KENC];                // permuted [n'][k], tf32-rounded
__device__ float g_benc[2][H4];
__device__ float g_Wdec[(size_t)NDEC * KDEC];         // permuted, tf32-rounded
__device__ float g_bdec[NDEC];
__device__ float g_win[NDEC];                         // permuted dec_Wih column
__device__ float g_fcw[H2];
__device__ float g_h[2][B * H2];                      // ping-pong hidden [b][1024]
__device__ float g_c[B * H2];                         // cell state (in-place safe)
__device__ float g_dpart[L_OUT * 32 * B];             // decoder fc partials [l][ntile][b]

// ---------------- helpers ----------------
__device__ __forceinline__ float tf32r(float x) {
    uint32_t u;
    asm("cvt.rna.tf32.f32 %0, %1;" : "=r"(u) : "f"(x));
    return __uint_as_float(u);
}
__device__ __forceinline__ float sigm(float x) { return 1.0f / (1.0f + expf(-x)); }

// ---------------- prep: transpose x, zero states ----------------
__global__ void prep_misc(const float* __restrict__ x) {
    int i = blockIdx.x * blockDim.x + threadIdx.x;
    if (i < T * B * F_IN) {
        int f = i & 127;         // F_IN = 128
        int r = i >> 7;          // t*B + b
        int b = r & 255;         // B = 256
        int t = r >> 8;
        g_xT[i] = x[((size_t)b * T + t) * F_IN + f];
    }
    if (i < B * H2) {
        g_h[0][i] = 0.0f;
        g_h[1][i] = 0.0f;
        g_c[i]    = 0.0f;
    }
}

// ---------------- prep: permute + tf32-round weights ----------------
// permuted column n' = 4*u + gate,  original row = gate*Hdim + u  (PyTorch i,f,g,o)
#define EW (2 * H4 * KENC)             // 2,621,440
#define DW (NDEC * KDEC)               // 4,194,304
#define PREP_TOT (EW + DW + 2 * H4 + NDEC + H2)

__global__ void prep_w(const float* __restrict__ eWih_f, const float* __restrict__ eWhh_f,
                       const float* __restrict__ ebih_f, const float* __restrict__ ebhh_f,
                       const float* __restrict__ eWih_b, const float* __restrict__ eWhh_b,
                       const float* __restrict__ ebih_b, const float* __restrict__ ebhh_b,
                       const float* __restrict__ dWih,   const float* __restrict__ dWhh,
                       const float* __restrict__ dbih,   const float* __restrict__ dbhh,
                       const float* __restrict__ fcW) {
    int i = blockIdx.x * blockDim.x + threadIdx.x;
    if (i >= PREP_TOT) return;

    if (i < EW) {
        int dir = i / (H4 * KENC);
        int r   = i - dir * (H4 * KENC);
        int n   = r / KENC;
        int k   = r - n * KENC;
        int u = n >> 2, gt = n & 3;
        int row = gt * H + u;
        const float* Wih = dir ? eWih_b : eWih_f;
        const float* Whh = dir ? eWhh_b : eWhh_f;
        float v = (k < F_IN) ? Wih[row * F_IN + k] : Whh[row * H + (k - F_IN)];
        g_Wenc[dir][n * KENC + k] = tf32r(v);
    } else if (i < EW + DW) {
        int r = i - EW;
        int n = r / KDEC;
        int k = r - n * KDEC;
        int u = n >> 2, gt = n & 3;
        int row = gt * H2 + u;
        g_Wdec[(size_t)n * KDEC + k] = tf32r(dWhh[(size_t)row * KDEC + k]);
    } else {
        int r = i - EW - DW;
        if (r < 2 * H4) {
            int dir = r >> 11;           // H4 = 2048
            int n = r & (H4 - 1);
            int u = n >> 2, gt = n & 3;
            int row = gt * H + u;
            g_benc[dir][n] = dir ? (ebih_b[row] + ebhh_b[row]) : (ebih_f[row] + ebhh_f[row]);
        } else if (r < 2 * H4 + NDEC) {
            int n = r - 2 * H4;
            int u = n >> 2, gt = n & 3;
            int row = gt * H2 + u;
            g_bdec[n] = dbih[row] + dbhh[row];
            g_win[n]  = dWih[row];       // dec_Wih is [NDEC, 1]
        } else {
            int u = r - 2 * H4 - NDEC;
            g_fcw[u] = fcW[u];
        }
    }
}

// ---------------- warp MMA on one K-chunk (tf32 m16n8k8) ----------------
__device__ __forceinline__ void mma_chunk(const float* __restrict__ As,
                                          const float* __restrict__ Bs,
                                          float (&acc)[2][4][4],
                                          int wm, int wn, int g, int tg) {
#pragma unroll
    for (int kb = 0; kb < KC; kb += 8) {
        uint32_t a[2][4];
#pragma unroll
        for (int mi = 0; mi < 2; mi++) {
            const float* ap = As + (wm * 32 + mi * 16 + g) * PAD + kb + tg;
            a[mi][0] = __float_as_uint(ap[0]);
            a[mi][1] = __float_as_uint(ap[8 * PAD]);
            a[mi][2] = __float_as_uint(ap[4]);
            a[mi][3] = __float_as_uint(ap[8 * PAD + 4]);
        }
#pragma unroll
        for (int ni = 0; ni < 4; ni++) {
            const float* bp = Bs + (wn * 32 + ni * 8 + g) * PAD + kb + tg;
            uint32_t b0 = __float_as_uint(bp[0]);
            uint32_t b1 = __float_as_uint(bp[4]);
#pragma unroll
            for (int mi = 0; mi < 2; mi++) {
                asm volatile(
                    "mma.sync.aligned.m16n8k8.row.col.f32.tf32.tf32.f32 "
                    "{%0,%1,%2,%3},{%4,%5,%6,%7},{%8,%9},{%0,%1,%2,%3};\n"
                    : "+f"(acc[mi][ni][0]), "+f"(acc[mi][ni][1]),
                      "+f"(acc[mi][ni][2]), "+f"(acc[mi][ni][3])
                    : "r"(a[mi][0]), "r"(a[mi][1]), "r"(a[mi][2]), "r"(a[mi][3]),
                      "r"(b0), "r"(b1));
            }
        }
    }
}

__device__ __forceinline__ void store_gates(float* __restrict__ Gs,
                                            float (&acc)[2][4][4],
                                            int wm, int wn, int g, int tg) {
#pragma unroll
    for (int mi = 0; mi < 2; mi++)
#pragma unroll
        for (int ni = 0; ni < 4; ni++) {
            int row = wm * 32 + mi * 16 + g;
            int col = wn * 32 + ni * 8 + 2 * tg;
            Gs[row * GSP + col]           = acc[mi][ni][0];
            Gs[row * GSP + col + 1]       = acc[mi][ni][1];
            Gs[(row + 8) * GSP + col]     = acc[mi][ni][2];
            Gs[(row + 8) * GSP + col + 1] = acc[mi][ni][3];
        }
}

// ---------------- encoder step: both directions, 128 CTAs ----------------
__global__ __launch_bounds__(256) void enc_step(int t, int p) {
    __shared__ float sm[SMTOT];
    float* As = sm;
    float* Bs = sm + BM * PAD;
    float* Gs = sm;     // reused after mainloop

    int bx  = blockIdx.x;
    int dir = bx >> 6;
    int mt  = (bx >> 4) & 3;
    int nt  = bx & 15;
    int m0 = mt * BM, n0 = nt * BN;
    int tid = threadIdx.x;
    int lane = tid & 31, wid = tid >> 5;
    int wm = wid & 1, wn = wid >> 1;
    int g = lane >> 2, tg = lane & 3;
    int tt = dir ? (T - 1 - t) : t;

    const float* W   = g_Wenc[dir];
    const float* hin = g_h[p];

    float acc[2][4][4];
#pragma unroll
    for (int a = 0; a < 2; a++)
#pragma unroll
        for (int bq = 0; bq < 4; bq++)
#pragma unroll
            for (int cq = 0; cq < 4; cq++) acc[a][bq][cq] = 0.0f;

    for (int ch = 0; ch < KENC / KC; ++ch) {
        int k0 = ch * KC;
        if (k0 < F_IN) {
            const float* xs = g_xT + ((size_t)tt * B + m0) * F_IN + k0;
            for (int i = tid; i < BM * KC; i += 256) {
                int m = i >> 5, kk = i & 31;
                As[m * PAD + kk] = tf32r(xs[m * F_IN + kk]);
            }
        } else {
            const float* hs = hin + (size_t)m0 * H2 + dir * H + (k0 - F_IN);
            for (int i = tid; i < BM * KC; i += 256) {
                int m = i >> 5, kk = i & 31;
                As[m * PAD + kk] = tf32r(hs[(size_t)m * H2 + kk]);
            }
        }
        const float* Wp = W + (size_t)n0 * KENC + k0;
        for (int i = tid; i < BN * KC; i += 256) {
            int n = i >> 5, kk = i & 31;
            Bs[n * PAD + kk] = Wp[(size_t)n * KENC + kk];
        }
        __syncthreads();
        mma_chunk(As, Bs, acc, wm, wn, g, tg);
        __syncthreads();
    }

    store_gates(Gs, acc, wm, wn, g, tg);
    __syncthreads();

    float* hout = g_h[p ^ 1];
    const float* bia = g_benc[dir] + n0;
    for (int i = tid; i < BM * 32; i += 256) {
        int m = i >> 5, uu = i & 31;
        int nn = 4 * uu;
        float gi = Gs[m * GSP + nn]     + bia[nn];
        float gf = Gs[m * GSP + nn + 1] + bia[nn + 1];
        float gg = Gs[m * GSP + nn + 2] + bia[nn + 2];
        float go = Gs[m * GSP + nn + 3] + bia[nn + 3];
        int cidx = (m0 + m) * H2 + dir * H + nt * 32 + uu;
        float ct = sigm(gf) * g_c[cidx] + sigm(gi) * tanhf(gg);
        g_c[cidx]  = ct;
        hout[cidx] = sigm(go) * tanhf(ct);
    }
}

// ---------------- decoder step: 128 CTAs ----------------
__global__ __launch_bounds__(256) void dec_step(int l, int p, const float* __restrict__ fcb) {
    __shared__ float sm[SMTOT];
    __shared__ float Hs[BM * 32];
    __shared__ float predS[BM];
    float* As = sm;
    float* Bs = sm + BM * PAD;
    float* Gs = sm;

    int bx = blockIdx.x;
    int mt = bx >> 5;
    int nt = bx & 31;
    int m0 = mt * BM, n0 = nt * BN;
    int tid = threadIdx.x;
    int lane = tid & 31, wid = tid >> 5;
    int wm = wid & 1, wn = wid >> 1;
    int g = lane >> 2, tg = lane & 3;

    // previous prediction per batch row (deterministic partial reduction)
    if (tid < BM) {
        float s = 0.0f;
        if (l > 0) {
            const float* dp = g_dpart + (l - 1) * 32 * B + (m0 + tid);
#pragma unroll
            for (int j = 0; j < 32; j++) s += dp[j * B];
            s += fcb[0];
        }
        predS[tid] = s;
    }

    const float* hin = g_h[p];

    float acc[2][4][4];
#pragma unroll
    for (int a = 0; a < 2; a++)
#pragma unroll
        for (int bq = 0; bq < 4; bq++)
#pragma unroll
            for (int cq = 0; cq < 4; cq++) acc[a][bq][cq] = 0.0f;

    for (int ch = 0; ch < KDEC / KC; ++ch) {
        int k0 = ch * KC;
        const float* hs = hin + (size_t)m0 * H2 + k0;
        for (int i = tid; i < BM * KC; i += 256) {
            int m = i >> 5, kk = i & 31;
            As[m * PAD + kk] = tf32r(hs[(size_t)m * H2 + kk]);
        }
        const float* Wp = g_Wdec + (size_t)n0 * KDEC + k0;
        for (int i = tid; i < BN * KC; i += 256) {
            int n = i >> 5, kk = i & 31;
            Bs[n * PAD + kk] = Wp[(size_t)n * KDEC + kk];
        }
        __syncthreads();
        mma_chunk(As, Bs, acc, wm, wn, g, tg);
        __syncthreads();
    }

    store_gates(Gs, acc, wm, wn, g, tg);
    __syncthreads();

    float* hout = g_h[p ^ 1];
    for (int i = tid; i < BM * 32; i += 256) {
        int m = i >> 5, uu = i & 31;
        int nn = 4 * uu;
        float pb = predS[m];
        float gi = Gs[m * GSP + nn]     + g_bdec[n0 + nn]     + pb * g_win[n0 + nn];
        float gf = Gs[m * GSP + nn + 1] + g_bdec[n0 + nn + 1] + pb * g_win[n0 + nn + 1];
        float gg = Gs[m * GSP + nn + 2] + g_bdec[n0 + nn + 2] + pb * g_win[n0 + nn + 2];
        float go = Gs[m * GSP + nn + 3] + g_bdec[n0 + nn + 3] + pb * g_win[n0 + nn + 3];
        int cidx = (m0 + m) * H2 + nt * 32 + uu;
        float ct = sigm(gf) * g_c[cidx] + sigm(gi) * tanhf(gg);
        g_c[cidx]  = ct;
        float ht = sigm(go) * tanhf(ct);
        hout[cidx] = ht;
        Hs[m * 32 + uu] = ht;
    }
    __syncthreads();

    // fc partial over this CTA's 32 units
    if (tid < BM) {
        float s = 0.0f;
        const float* fw = g_fcw + nt * 32;
        const float* hh = Hs + tid * 32;
#pragma unroll
        for (int j = 0; j < 32; j++) s += fw[j] * hh[j];
        g_dpart[(l * 32 + nt) * B + m0 + tid] = s;
    }
}

// ---------------- finalize: out[b][l] = sum partials + fc_b ----------------
__global__ void finalize(float* __restrict__ out, const float* __restrict__ fcb) {
    int i = blockIdx.x * blockDim.x + threadIdx.x;
    if (i < B * L_OUT) {
        int b = i / L_OUT;
        int l = i - b * L_OUT;
        float s = fcb[0];
#pragma unroll
        for (int j = 0; j < 32; j++) s += g_dpart[(l * 32 + j) * B + b];
        out[i] = s;
    }
}

// ---------------- launch ----------------
extern "C" void kernel_launch(void* const* d_in, const int* in_sizes, int n_in,
                              void* d_out, int out_size) {
    const float* x      = (const float*)d_in[0];
    const float* eWih_f = (const float*)d_in[1];
    const float* eWhh_f = (const float*)d_in[2];
    const float* ebih_f = (const float*)d_in[3];
    const float* ebhh_f = (const float*)d_in[4];
    const float* eWih_b = (const float*)d_in[5];
    const float* eWhh_b = (const float*)d_in[6];
    const float* ebih_b = (const float*)d_in[7];
    const float* ebhh_b = (const float*)d_in[8];
    const float* dWih   = (const float*)d_in[9];
    const float* dWhh   = (const float*)d_in[10];
    const float* dbih   = (const float*)d_in[11];
    const float* dbhh   = (const float*)d_in[12];
    const float* fcW    = (const float*)d_in[13];
    const float* fcb    = (const float*)d_in[14];

    prep_misc<<<(T * B * F_IN + 255) / 256, 256>>>(x);
    prep_w<<<(PREP_TOT + 255) / 256, 256>>>(eWih_f, eWhh_f, ebih_f, ebhh_f,
                                            eWih_b, eWhh_b, ebih_b, ebhh_b,
                                            dWih, dWhh, dbih, dbhh, fcW);

    for (int t = 0; t < T; t++)
        enc_step<<<128, 256>>>(t, t & 1);

    for (int l = 0; l < L_OUT; l++)
        dec_step<<<128, 256>>>(l, l & 1, fcb);

    finalize<<<(B * L_OUT + 255) / 256, 256>>>((float*)d_out, fcb);
}

// round 6
// speedup vs baseline: 2.5393x; 2.5393x over previous
#include <cuda_runtime.h>
#include <cstdint>
#include <math.h>

// ---------------- problem constants ----------------
#define B      256
#define T      168
#define F_IN   128
#define H      512
#define H4     2048      // 4*H (encoder gates per direction)
#define KENC   640       // F_IN + H
#define H2     1024      // decoder hidden (2H)
#define NDEC   4096      // 4 * H2
#define KDEC   1024
#define L_OUT  48

// ---------------- GEMM tiling ----------------
#define BM     64
#define BN     128
#define KC     64
#define PADK   68        // smem row stride (floats); 68 mod 32 = 4 -> conflict-free frags
#define GSP    129       // gate staging row stride
#define STG    ((BM + BN) * PADK)   // 13056 floats per pipeline stage
#define STAGES 3
#define DYNB   (STAGES * STG * 4)   // 156672 bytes dynamic smem
#define NCTA   128
#define NCHE   (KENC / KC)          // 10
#define NCHD   (KDEC / KC)          // 16

// ---------------- device scratch ----------------
__device__ __align__(16) float g_xT[(size_t)T * B * F_IN];   // [t][b][f], tf32-rounded
__device__ __align__(16) float g_Wenc[2][H4 * KENC];         // permuted [n'][k], tf32
__device__ __align__(16) float g_benc[2][H4];
__device__ __align__(16) float g_Wdec[(size_t)NDEC * KDEC];  // permuted, tf32
__device__ __align__(16) float g_bdec[NDEC];
__device__ __align__(16) float g_win[NDEC];
__device__ __align__(16) float g_fcw[H2];
__device__ __align__(16) float g_h[2][B * H2];               // ping-pong hidden (tf32)
__device__ __align__(16) float g_c[B * H2];
__device__ __align__(16) float g_dpart[L_OUT * 32 * B];      // fc partials [l][ntile][b]

__device__ unsigned g_cnt = 0;
__device__ volatile unsigned g_gen = 0;

// ---------------- helpers ----------------
__device__ __forceinline__ float tf32r(float x) {
    uint32_t u;
    asm("cvt.rna.tf32.f32 %0, %1;" : "=r"(u) : "f"(x));
    return __uint_as_float(u);
}
__device__ __forceinline__ float fsigm(float x) {
    return __fdividef(1.0f, 1.0f + __expf(-x));
}
__device__ __forceinline__ float ftanh(float x) {
    return __fdividef(2.0f, 1.0f + __expf(-2.0f * x)) - 1.0f;
}

__device__ __forceinline__ void gsync() {
    __threadfence();          // all threads: make this CTA's stores visible
    __syncthreads();
    if (threadIdx.x == 0) {
        unsigned g = g_gen;
        if (atomicAdd(&g_cnt, 1u) == NCTA - 1u) {
            g_cnt = 0u;
            __threadfence();
            g_gen = g + 1u;
        } else {
            while (g_gen == g) __nanosleep(32);
            __threadfence();
        }
    }
    __syncthreads();
}

// cp.async: .ca for read-only data written before this launch; .cg (L2-only)
// for h, whose ping-pong addresses are rewritten each step by other SMs.
__device__ __forceinline__ void cpa16_ca(uint32_t dst, const float* src) {
    asm volatile("cp.async.ca.shared.global [%0], [%1], 16;\n" :: "r"(dst), "l"(src));
}
__device__ __forceinline__ void cpa16_cg(uint32_t dst, const float* src) {
    asm volatile("cp.async.cg.shared.global [%0], [%1], 16;\n" :: "r"(dst), "l"(src));
}
#define CP_COMMIT() asm volatile("cp.async.commit_group;\n" ::: "memory")
#define CP_WAIT1()  asm volatile("cp.async.wait_group 1;\n" ::: "memory")

// load one (A,B) K-chunk into stage `su` (shared addr). a_cg: use .cg for A.
__device__ __forceinline__ void load_chunk(uint32_t su,
                                           const float* __restrict__ asrc, int astride, int a_cg,
                                           const float* __restrict__ bsrc, int bstride,
                                           int tid) {
#pragma unroll
    for (int i = tid; i < BM * 16; i += 256) {
        int r = i >> 4, v = i & 15;
        uint32_t d = su + (uint32_t)(r * PADK + v * 4) * 4u;
        const float* s = asrc + (size_t)r * astride + v * 4;
        if (a_cg) cpa16_cg(d, s); else cpa16_ca(d, s);
    }
    uint32_t bu = su + (uint32_t)(BM * PADK) * 4u;
#pragma unroll
    for (int i = tid; i < BN * 16; i += 256) {
        int r = i >> 4, v = i & 15;
        cpa16_ca(bu + (uint32_t)(r * PADK + v * 4) * 4u, bsrc + (size_t)r * bstride + v * 4);
    }
}

// ---------------- warp MMA on one K-chunk (tf32 m16n8k8) ----------------
__device__ __forceinline__ void mma_chunk(const float* __restrict__ As,
                                          const float* __restrict__ Bs,
                                          float (&acc)[2][4][4],
                                          int wm, int wn, int g, int tg) {
#pragma unroll
    for (int kb = 0; kb < KC; kb += 8) {
        uint32_t a[2][4];
#pragma unroll
        for (int mi = 0; mi < 2; mi++) {
            const float* ap = As + (wm * 32 + mi * 16 + g) * PADK + kb + tg;
            a[mi][0] = __float_as_uint(ap[0]);
            a[mi][1] = __float_as_uint(ap[8 * PADK]);
            a[mi][2] = __float_as_uint(ap[4]);
            a[mi][3] = __float_as_uint(ap[8 * PADK + 4]);
        }
#pragma unroll
        for (int ni = 0; ni < 4; ni++) {
            const float* bp = Bs + (wn * 32 + ni * 8 + g) * PADK + kb + tg;
            uint32_t b0 = __float_as_uint(bp[0]);
            uint32_t b1 = __float_as_uint(bp[4]);
#pragma unroll
            for (int mi = 0; mi < 2; mi++) {
                asm volatile(
                    "mma.sync.aligned.m16n8k8.row.col.f32.tf32.tf32.f32 "
                    "{%0,%1,%2,%3},{%4,%5,%6,%7},{%8,%9},{%0,%1,%2,%3};\n"
                    : "+f"(acc[mi][ni][0]), "+f"(acc[mi][ni][1]),
                      "+f"(acc[mi][ni][2]), "+f"(acc[mi][ni][3])
                    : "r"(a[mi][0]), "r"(a[mi][1]), "r"(a[mi][2]), "r"(a[mi][3]),
                      "r"(b0), "r"(b1));
            }
        }
    }
}

__device__ __forceinline__ void store_gates(float* __restrict__ Gs,
                                            float (&acc)[2][4][4],
                                            int wm, int wn, int g, int tg) {
#pragma unroll
    for (int mi = 0; mi < 2; mi++)
#pragma unroll
        for (int ni = 0; ni < 4; ni++) {
            int row = wm * 32 + mi * 16 + g;
            int col = wn * 32 + ni * 8 + 2 * tg;
            Gs[row * GSP + col]           = acc[mi][ni][0];
            Gs[row * GSP + col + 1]       = acc[mi][ni][1];
            Gs[(row + 8) * GSP + col]     = acc[mi][ni][2];
            Gs[(row + 8) * GSP + col + 1] = acc[mi][ni][3];
        }
}

// ---------------- prep ----------------
__global__ void prep_misc(const float* __restrict__ x) {
    int i = blockIdx.x * blockDim.x + threadIdx.x;
    if (i < T * B * F_IN) {
        int f = i & 127;
        int r = i >> 7;
        int b = r & 255;
        int t = r >> 8;
        g_xT[i] = tf32r(x[((size_t)b * T + t) * F_IN + f]);
    }
    if (i < B * H2) {
        g_h[0][i] = 0.0f;
        g_h[1][i] = 0.0f;
    }
}

#define EW (2 * H4 * KENC)
#define DW (NDEC * KDEC)
#define PREP_TOT (EW + DW + 2 * H4 + NDEC + H2)

__global__ void prep_w(const float* __restrict__ eWih_f, const float* __restrict__ eWhh_f,
                       const float* __restrict__ ebih_f, const float* __restrict__ ebhh_f,
                       const float* __restrict__ eWih_b, const float* __restrict__ eWhh_b,
                       const float* __restrict__ ebih_b, const float* __restrict__ ebhh_b,
                       const float* __restrict__ dWih,   const float* __restrict__ dWhh,
                       const float* __restrict__ dbih,   const float* __restrict__ dbhh,
                       const float* __restrict__ fcW) {
    int i = blockIdx.x * blockDim.x + threadIdx.x;
    if (i >= PREP_TOT) return;

    if (i < EW) {
        int dir = i / (H4 * KENC);
        int r   = i - dir * (H4 * KENC);
        int n   = r / KENC;
        int k   = r - n * KENC;
        int u = n >> 2, gt = n & 3;
        int row = gt * H + u;
        const float* Wih = dir ? eWih_b : eWih_f;
        const float* Whh = dir ? eWhh_b : eWhh_f;
        float v = (k < F_IN) ? Wih[row * F_IN + k] : Whh[row * H + (k - F_IN)];
        g_Wenc[dir][n * KENC + k] = tf32r(v);
    } else if (i < EW + DW) {
        int r = i - EW;
        int n = r / KDEC;
        int k = r - n * KDEC;
        int u = n >> 2, gt = n & 3;
        int row = gt * H2 + u;
        g_Wdec[(size_t)n * KDEC + k] = tf32r(dWhh[(size_t)row * KDEC + k]);
    } else {
        int r = i - EW - DW;
        if (r < 2 * H4) {
            int dir = r >> 11;
            int n = r & (H4 - 1);
            int u = n >> 2, gt = n & 3;
            int row = gt * H + u;
            g_benc[dir][n] = dir ? (ebih_b[row] + ebhh_b[row]) : (ebih_f[row] + ebhh_f[row]);
        } else if (r < 2 * H4 + NDEC) {
            int n = r - 2 * H4;
            int u = n >> 2, gt = n & 3;
            int row = gt * H2 + u;
            g_bdec[n] = dbih[row] + dbhh[row];
            g_win[n]  = dWih[row];
        } else {
            int u = r - 2 * H4 - NDEC;
            g_fcw[u] = fcW[u];
        }
    }
}

// ---------------- persistent kernel: encoder + decoder + finalize ----------------
__global__ __launch_bounds__(256, 1) void persist(float* __restrict__ out,
                                                  const float* __restrict__ fcb) {
    extern __shared__ float dyn[];
    __shared__ float cS[BM * 32];
    __shared__ float sBias[BN];
    __shared__ float sWin[BN];
    __shared__ float sFc[32];
    __shared__ float predS[BM];
    __shared__ float predP[BM][4];

    uint32_t dynu = (uint32_t)__cvta_generic_to_shared(dyn);
    int bx = blockIdx.x;
    int tid = threadIdx.x;
    int lane = tid & 31, wid = tid >> 5;
    int wm = wid & 1, wn = wid >> 1;
    int g = lane >> 2, tg = lane & 3;
    float fcb0 = fcb[0];

    // =============== encoder (both dirs across 128 CTAs) ===============
    {
        int dir = bx >> 6;
        int mt  = (bx >> 4) & 3;
        int nt  = bx & 15;
        int m0 = mt * BM, n0 = nt * BN;
        const float* W = g_Wenc[dir] + (size_t)n0 * KENC;

        for (int i = tid; i < BM * 32; i += 256) cS[i] = 0.0f;
        if (tid < BN) sBias[tid] = g_benc[dir][n0 + tid];
        __syncthreads();

        for (int t = 0; t < T; t++) {
            int p = t & 1;
            int tt = dir ? (T - 1 - t) : t;
            const float* xb = g_xT + ((size_t)tt * B + m0) * F_IN;
            const float* hb = g_h[p] + (size_t)m0 * H2 + dir * H;
            float* hout = g_h[p ^ 1];

            float acc[2][4][4];
#pragma unroll
            for (int a = 0; a < 2; a++)
#pragma unroll
                for (int bq = 0; bq < 4; bq++)
#pragma unroll
                    for (int cq = 0; cq < 4; cq++) acc[a][bq][cq] = 0.0f;

#pragma unroll
            for (int s = 0; s < 2; s++) {
                int k0 = s * KC;
                if (k0 < F_IN)
                    load_chunk(dynu + (uint32_t)(s * STG) * 4u, xb + k0, F_IN, 0, W + k0, KENC, tid);
                else
                    load_chunk(dynu + (uint32_t)(s * STG) * 4u, hb + (k0 - F_IN), H2, 1, W + k0, KENC, tid);
                CP_COMMIT();
            }
            for (int ch = 0; ch < NCHE; ch++) {
                CP_WAIT1();
                __syncthreads();
                int pf = ch + 2;
                if (pf < NCHE) {
                    int k0 = pf * KC;
                    uint32_t su = dynu + (uint32_t)((pf % 3) * STG) * 4u;
                    if (k0 < F_IN)
                        load_chunk(su, xb + k0, F_IN, 0, W + k0, KENC, tid);
                    else
                        load_chunk(su, hb + (k0 - F_IN), H2, 1, W + k0, KENC, tid);
                }
                CP_COMMIT();
                float* st = dyn + (ch % 3) * STG;
                mma_chunk(st, st + BM * PADK, acc, wm, wn, g, tg);
            }
            __syncthreads();
            store_gates(dyn, acc, wm, wn, g, tg);
            __syncthreads();
            for (int i = tid; i < BM * 32; i += 256) {
                int m = i >> 5, uu = i & 31;
                int nn = 4 * uu;
                float gi = dyn[m * GSP + nn]     + sBias[nn];
                float gf = dyn[m * GSP + nn + 1] + sBias[nn + 1];
                float gg = dyn[m * GSP + nn + 2] + sBias[nn + 2];
                float go = dyn[m * GSP + nn + 3] + sBias[nn + 3];
                float ct = fsigm(gf) * cS[i] + fsigm(gi) * ftanh(gg);
                cS[i] = ct;
                hout[(size_t)(m0 + m) * H2 + dir * H + nt * 32 + uu] = tf32r(fsigm(go) * ftanh(ct));
            }
            gsync();
        }
        // flush c for decoder re-tiling
        for (int i = tid; i < BM * 32; i += 256) {
            int m = i >> 5, uu = i & 31;
            g_c[(size_t)(m0 + m) * H2 + dir * H + nt * 32 + uu] = cS[i];
        }
        gsync();
    }

    // =============== decoder ===============
    {
        int mt = bx >> 5, nt = bx & 31;
        int m0 = mt * BM, n0 = nt * BN;
        const float* W = g_Wdec + (size_t)n0 * KDEC;

        for (int i = tid; i < BM * 32; i += 256) {
            int m = i >> 5, uu = i & 31;
            cS[i] = g_c[(size_t)(m0 + m) * H2 + nt * 32 + uu];
        }
        if (tid < BN) { sBias[tid] = g_bdec[n0 + tid]; sWin[tid] = g_win[n0 + tid]; }
        if (tid < 32) sFc[tid] = g_fcw[nt * 32 + tid];
        __syncthreads();

        for (int l = 0; l < L_OUT; l++) {
            int p = l & 1;
            const float* hbase = g_h[p] + (size_t)m0 * H2;
            float* hout = g_h[p ^ 1];

            float acc[2][4][4];
#pragma unroll
            for (int a = 0; a < 2; a++)
#pragma unroll
                for (int bq = 0; bq < 4; bq++)
#pragma unroll
                    for (int cq = 0; cq < 4; cq++) acc[a][bq][cq] = 0.0f;

#pragma unroll
            for (int s = 0; s < 2; s++) {
                load_chunk(dynu + (uint32_t)(s * STG) * 4u, hbase + s * KC, H2, 1,
                           W + s * KC, KDEC, tid);
                CP_COMMIT();
            }
            // overlap: previous prediction partials (deterministic order)
            {
                int r = tid >> 2, q = tid & 3;
                float s = 0.0f;
                if (l > 0) {
                    const float* dp = g_dpart + (size_t)(l - 1) * 32 * B + m0 + r;
#pragma unroll
                    for (int j = 0; j < 8; j++) s += dp[(q * 8 + j) * B];
                }
                predP[r][q] = s;
            }
            for (int ch = 0; ch < NCHD; ch++) {
                CP_WAIT1();
                __syncthreads();
                int pf = ch + 2;
                if (pf < NCHD)
                    load_chunk(dynu + (uint32_t)((pf % 3) * STG) * 4u, hbase + pf * KC, H2, 1,
                               W + pf * KC, KDEC, tid);
                CP_COMMIT();
                float* st = dyn + (ch % 3) * STG;
                mma_chunk(st, st + BM * PADK, acc, wm, wn, g, tg);
            }
            __syncthreads();
            if (tid < BM)
                predS[tid] = (l > 0)
                    ? (predP[tid][0] + predP[tid][1] + predP[tid][2] + predP[tid][3] + fcb0)
                    : 0.0f;
            store_gates(dyn, acc, wm, wn, g, tg);
            __syncthreads();
            float* Hs = dyn + BM * GSP;
            for (int i = tid; i < BM * 32; i += 256) {
                int m = i >> 5, uu = i & 31;
                int nn = 4 * uu;
                float pb = predS[m];
                float gi = dyn[m * GSP + nn]     + sBias[nn]     + pb * sWin[nn];
                float gf = dyn[m * GSP + nn + 1] + sBias[nn + 1] + pb * sWin[nn + 1];
                float gg = dyn[m * GSP + nn + 2] + sBias[nn + 2] + pb * sWin[nn + 2];
                float go = dyn[m * GSP + nn + 3] + sBias[nn + 3] + pb * sWin[nn + 3];
                float ct = fsigm(gf) * cS[i] + fsigm(gi) * ftanh(gg);
                cS[i] = ct;
                float ht = fsigm(go) * ftanh(ct);
                hout[(size_t)(m0 + m) * H2 + nt * 32 + uu] = tf32r(ht);
                Hs[i] = ht;
            }
            __syncthreads();
            if (tid < BM) {
                float s = 0.0f;
#pragma unroll
                for (int j = 0; j < 32; j++) s += sFc[j] * Hs[tid * 32 + j];
                g_dpart[(size_t)(l * 32 + nt) * B + m0 + tid] = s;
            }
            gsync();
        }
    }

    // =============== finalize ===============
    {
        int idx = bx * 256 + tid;
        if (idx < B * L_OUT) {
            int b = idx / L_OUT, l = idx - b * L_OUT;
            float s = fcb0;
#pragma unroll
            for (int j = 0; j < 32; j++) s += g_dpart[(size_t)(l * 32 + j) * B + b];
            out[idx] = s;
        }
    }
}

// ---------------- launch ----------------
extern "C" void kernel_launch(void* const* d_in, const int* in_sizes, int n_in,
                              void* d_out, int out_size) {
    const float* x      = (const float*)d_in[0];
    const float* eWih_f = (const float*)d_in[1];
    const float* eWhh_f = (const float*)d_in[2];
    const float* ebih_f = (const float*)d_in[3];
    const float* ebhh_f = (const float*)d_in[4];
    const float* eWih_b = (const float*)d_in[5];
    const float* eWhh_b = (const float*)d_in[6];
    const float* ebih_b = (const float*)d_in[7];
    const float* ebhh_b = (const float*)d_in[8];
    const float* dWih   = (const float*)d_in[9];
    const float* dWhh   = (const float*)d_in[10];
    const float* dbih   = (const float*)d_in[11];
    const float* dbhh   = (const float*)d_in[12];
    const float* fcW    = (const float*)d_in[13];
    const float* fcb    = (const float*)d_in[14];

    cudaFuncSetAttribute(persist, cudaFuncAttributeMaxDynamicSharedMemorySize, DYNB);

    prep_misc<<<(T * B * F_IN + 255) / 256, 256>>>(x);
    prep_w<<<(PREP_TOT + 255) / 256, 256>>>(eWih_f, eWhh_f, ebih_f, ebhh_f,
                                            eWih_b, eWhh_b, ebih_b, ebhh_b,
                                            dWih, dWhh, dbih, dbhh, fcW);
    persist<<<NCTA, 256, DYNB>>>((float*)d_out, fcb);
}

// round 7
// speedup vs baseline: 2.8512x; 1.1228x over previous
#include <cuda_runtime.h>
#include <cuda_fp16.h>
#include <cstdint>
#include <math.h>

// ---------------- problem constants ----------------
#define B      256
#define T      168
#define F_IN   128
#define H      512
#define H4     2048      // 4*H (encoder gates per direction)
#define KENC   640       // F_IN + H
#define H2     1024      // decoder hidden (2H)
#define NDEC   4096      // 4 * H2
#define KDEC   1024
#define L_OUT  48

// ---------------- GEMM tiling (fp16 operands, f32 accum) ----------------
#define BM     64
#define BN     128
#define KC     128       // K per chunk (halves)
#define PADH   136       // smem row stride in halves; (136/2)%32=4 -> conflict-free frags
#define GSP    132       // gate staging row stride (floats, 4-aligned for float4)
#define HSP    33        // Hs staging row stride (floats)
#define STG_H  ((BM + BN) * PADH)     // 26112 halves per pipeline stage
#define STAGES 3
#define DYNB   (STAGES * STG_H * 2)   // 156672 bytes dynamic smem
#define NCTA   128
#define NCHE   (KENC / KC)            // 5
#define NCHD   (KDEC / KC)            // 8

// ---------------- device scratch ----------------
__device__ __align__(16) __half g_xT[(size_t)T * B * F_IN];   // [t][b][f], fp16
__device__ __align__(16) __half g_Wenc[2][H4 * KENC];         // permuted [n'][k], fp16
__device__ __align__(16) float  g_benc[2][H4];
__device__ __align__(16) __half g_Wdec[(size_t)NDEC * KDEC];  // permuted, fp16
__device__ __align__(16) float  g_bdec[NDEC];
__device__ __align__(16) float  g_win[NDEC];
__device__ __align__(16) float  g_fcw[H2];
__device__ __align__(16) __half g_h[2][B * H2];               // ping-pong hidden (fp16)
__device__ __align__(16) float  g_c[B * H2];
__device__ __align__(16) float  g_dpart[L_OUT * 32 * B];      // fc partials [l][ntile][b]

__device__ unsigned g_cnt = 0;
__device__ volatile unsigned g_gen = 0;

// ---------------- helpers ----------------
__device__ __forceinline__ float fsigm(float x) {
    return __fdividef(1.0f, 1.0f + __expf(-x));
}
__device__ __forceinline__ float ftanh(float x) {
    return __fdividef(2.0f, 1.0f + __expf(-2.0f * x)) - 1.0f;
}

__device__ __forceinline__ void gsync() {
    __threadfence();
    __syncthreads();
    if (threadIdx.x == 0) {
        unsigned g = g_gen;
        if (atomicAdd(&g_cnt, 1u) == NCTA - 1u) {
            g_cnt = 0u;
            __threadfence();
            g_gen = g + 1u;
        } else {
            while (g_gen == g) __nanosleep(32);
            __threadfence();
        }
    }
    __syncthreads();
}

// cp.async: .ca for data static during this kernel; .cg (L2-only) for h,
// whose ping-pong addresses are rewritten each step by other SMs.
__device__ __forceinline__ void cpa16_ca(uint32_t dst, const __half* src) {
    asm volatile("cp.async.ca.shared.global [%0], [%1], 16;\n" :: "r"(dst), "l"(src));
}
__device__ __forceinline__ void cpa16_cg(uint32_t dst, const __half* src) {
    asm volatile("cp.async.cg.shared.global [%0], [%1], 16;\n" :: "r"(dst), "l"(src));
}
#define CP_COMMIT() asm volatile("cp.async.commit_group;\n" ::: "memory")
#define CP_WAIT1()  asm volatile("cp.async.wait_group 1;\n" ::: "memory")

// load one (A,B) K-chunk (KC=128 halves per row) into stage at shared addr su
__device__ __forceinline__ void load_chunk(uint32_t su,
                                           const __half* __restrict__ asrc, int astride, int a_cg,
                                           const __half* __restrict__ bsrc, int bstride,
                                           int tid) {
#pragma unroll
    for (int i = tid; i < BM * 16; i += 256) {
        int r = i >> 4, v = i & 15;
        uint32_t d = su + (uint32_t)(r * PADH + v * 8) * 2u;
        const __half* s = asrc + (size_t)r * astride + v * 8;
        if (a_cg) cpa16_cg(d, s); else cpa16_ca(d, s);
    }
    uint32_t bu = su + (uint32_t)(BM * PADH) * 2u;
#pragma unroll
    for (int i = tid; i < BN * 16; i += 256) {
        int r = i >> 4, v = i & 15;
        cpa16_ca(bu + (uint32_t)(r * PADH + v * 8) * 2u, bsrc + (size_t)r * bstride + v * 8);
    }
}

// ---------------- warp MMA on one K-chunk (fp16 m16n8k16, f32 accum) ----------------
__device__ __forceinline__ void mma_chunk(const __half* __restrict__ As,
                                          const __half* __restrict__ Bs,
                                          float (&acc)[2][4][4],
                                          int wm, int wn, int g, int tg) {
#pragma unroll
    for (int kb = 0; kb < KC; kb += 16) {
        uint32_t a[2][4];
#pragma unroll
        for (int mi = 0; mi < 2; mi++) {
            const __half* ap = As + (wm * 32 + mi * 16 + g) * PADH + kb + 2 * tg;
            a[mi][0] = *(const uint32_t*)(ap);
            a[mi][1] = *(const uint32_t*)(ap + 8 * PADH);
            a[mi][2] = *(const uint32_t*)(ap + 8);
            a[mi][3] = *(const uint32_t*)(ap + 8 * PADH + 8);
        }
#pragma unroll
        for (int ni = 0; ni < 4; ni++) {
            const __half* bp = Bs + (wn * 32 + ni * 8 + g) * PADH + kb + 2 * tg;
            uint32_t b0 = *(const uint32_t*)(bp);
            uint32_t b1 = *(const uint32_t*)(bp + 8);
#pragma unroll
            for (int mi = 0; mi < 2; mi++) {
                asm volatile(
                    "mma.sync.aligned.m16n8k16.row.col.f32.f16.f16.f32 "
                    "{%0,%1,%2,%3},{%4,%5,%6,%7},{%8,%9},{%0,%1,%2,%3};\n"
                    : "+f"(acc[mi][ni][0]), "+f"(acc[mi][ni][1]),
                      "+f"(acc[mi][ni][2]), "+f"(acc[mi][ni][3])
                    : "r"(a[mi][0]), "r"(a[mi][1]), "r"(a[mi][2]), "r"(a[mi][3]),
                      "r"(b0), "r"(b1));
            }
        }
    }
}

__device__ __forceinline__ void store_gates(float* __restrict__ Gs,
                                            float (&acc)[2][4][4],
                                            int wm, int wn, int g, int tg) {
#pragma unroll
    for (int mi = 0; mi < 2; mi++)
#pragma unroll
        for (int ni = 0; ni < 4; ni++) {
            int row = wm * 32 + mi * 16 + g;
            int col = wn * 32 + ni * 8 + 2 * tg;
            Gs[row * GSP + col]           = acc[mi][ni][0];
            Gs[row * GSP + col + 1]       = acc[mi][ni][1];
            Gs[(row + 8) * GSP + col]     = acc[mi][ni][2];
            Gs[(row + 8) * GSP + col + 1] = acc[mi][ni][3];
        }
}

// ---------------- prep ----------------
__global__ void prep_misc(const float* __restrict__ x) {
    int i = blockIdx.x * blockDim.x + threadIdx.x;
    if (i < T * B * F_IN) {
        int f = i & 127;
        int r = i >> 7;
        int b = r & 255;
        int t = r >> 8;
        g_xT[i] = __float2half(x[((size_t)b * T + t) * F_IN + f]);
    }
    if (i < B * H2) {
        g_h[0][i] = __half(0.0f);
        g_h[1][i] = __half(0.0f);
    }
}

#define EW (2 * H4 * KENC)
#define DW (NDEC * KDEC)
#define PREP_TOT (EW + DW + 2 * H4 + NDEC + H2)

__global__ void prep_w(const float* __restrict__ eWih_f, const float* __restrict__ eWhh_f,
                       const float* __restrict__ ebih_f, const float* __restrict__ ebhh_f,
                       const float* __restrict__ eWih_b, const float* __restrict__ eWhh_b,
                       const float* __restrict__ ebih_b, const float* __restrict__ ebhh_b,
                       const float* __restrict__ dWih,   const float* __restrict__ dWhh,
                       const float* __restrict__ dbih,   const float* __restrict__ dbhh,
                       const float* __restrict__ fcW) {
    int i = blockIdx.x * blockDim.x + threadIdx.x;
    if (i >= PREP_TOT) return;

    if (i < EW) {
        int dir = i / (H4 * KENC);
        int r   = i - dir * (H4 * KENC);
        int n   = r / KENC;
        int k   = r - n * KENC;
        int u = n >> 2, gt = n & 3;
        int row = gt * H + u;
        const float* Wih = dir ? eWih_b : eWih_f;
        const float* Whh = dir ? eWhh_b : eWhh_f;
        float v = (k < F_IN) ? Wih[row * F_IN + k] : Whh[row * H + (k - F_IN)];
        g_Wenc[dir][n * KENC + k] = __float2half(v);
    } else if (i < EW + DW) {
        int r = i - EW;
        int n = r / KDEC;
        int k = r - n * KDEC;
        int u = n >> 2, gt = n & 3;
        int row = gt * H2 + u;
        g_Wdec[(size_t)n * KDEC + k] = __float2half(dWhh[(size_t)row * KDEC + k]);
    } else {
        int r = i - EW - DW;
        if (r < 2 * H4) {
            int dir = r >> 11;
            int n = r & (H4 - 1);
            int u = n >> 2, gt = n & 3;
            int row = gt * H + u;
            g_benc[dir][n] = dir ? (ebih_b[row] + ebhh_b[row]) : (ebih_f[row] + ebhh_f[row]);
        } else if (r < 2 * H4 + NDEC) {
            int n = r - 2 * H4;
            int u = n >> 2, gt = n & 3;
            int row = gt * H2 + u;
            g_bdec[n] = dbih[row] + dbhh[row];
            g_win[n]  = dWih[row];
        } else {
            int u = r - 2 * H4 - NDEC;
            g_fcw[u] = fcW[u];
        }
    }
}

// ---------------- persistent kernel: encoder + decoder + finalize ----------------
__global__ __launch_bounds__(256, 1) void persist(float* __restrict__ out,
                                                  const float* __restrict__ fcb) {
    extern __shared__ __half dyn[];
    float* dynf = reinterpret_cast<float*>(dyn);
    __shared__ float cS[BM * 32];
    __shared__ float sBias[BN];
    __shared__ float sWin[BN];
    __shared__ float sFc[32];
    __shared__ float predS[BM];
    __shared__ float predP[BM][4];

    uint32_t dynu = (uint32_t)__cvta_generic_to_shared(dyn);
    int bx = blockIdx.x;
    int tid = threadIdx.x;
    int lane = tid & 31, wid = tid >> 5;
    int wm = wid & 1, wn = wid >> 1;
    int g = lane >> 2, tg = lane & 3;
    float fcb0 = fcb[0];

    // =============== encoder (both dirs across 128 CTAs) ===============
    {
        int dir = bx >> 6;
        int mt  = (bx >> 4) & 3;
        int nt  = bx & 15;
        int m0 = mt * BM, n0 = nt * BN;
        const __half* W = g_Wenc[dir] + (size_t)n0 * KENC;

        for (int i = tid; i < BM * 32; i += 256) cS[i] = 0.0f;
        if (tid < BN) sBias[tid] = g_benc[dir][n0 + tid];
        __syncthreads();

        for (int t = 0; t < T; t++) {
            int p = t & 1;
            int tt = dir ? (T - 1 - t) : t;
            const __half* xb = g_xT + ((size_t)tt * B + m0) * F_IN;
            const __half* hb = g_h[p] + (size_t)m0 * H2 + dir * H;
            __half* hout = g_h[p ^ 1];

            float acc[2][4][4];
#pragma unroll
            for (int a = 0; a < 2; a++)
#pragma unroll
                for (int bq = 0; bq < 4; bq++)
#pragma unroll
                    for (int cq = 0; cq < 4; cq++) acc[a][bq][cq] = 0.0f;

            // chunk 0 = x (K=128 exactly), chunks 1..4 = h
            load_chunk(dynu, xb, F_IN, 0, W, KENC, tid);
            CP_COMMIT();
            load_chunk(dynu + (uint32_t)STG_H * 2u, hb, H2, 1, W + KC, KENC, tid);
            CP_COMMIT();

            for (int ch = 0; ch < NCHE; ch++) {
                CP_WAIT1();
                __syncthreads();
                int pf = ch + 2;
                if (pf < NCHE) {
                    int k0 = pf * KC;
                    load_chunk(dynu + (uint32_t)((pf % 3) * STG_H) * 2u,
                               hb + (k0 - F_IN), H2, 1, W + k0, KENC, tid);
                }
                CP_COMMIT();
                const __half* st = dyn + (ch % 3) * STG_H;
                mma_chunk(st, st + BM * PADH, acc, wm, wn, g, tg);
            }
            __syncthreads();
            store_gates(dynf, acc, wm, wn, g, tg);
            __syncthreads();
            for (int i = tid; i < BM * 32; i += 256) {
                int m = i >> 5, uu = i & 31;
                float4 gv = *reinterpret_cast<const float4*>(dynf + m * GSP + 4 * uu);
                int nn = 4 * uu;
                float gi = gv.x + sBias[nn];
                float gf = gv.y + sBias[nn + 1];
                float gg = gv.z + sBias[nn + 2];
                float go = gv.w + sBias[nn + 3];
                float ct = fsigm(gf) * cS[i] + fsigm(gi) * ftanh(gg);
                cS[i] = ct;
                hout[(size_t)(m0 + m) * H2 + dir * H + nt * 32 + uu] =
                    __float2half(fsigm(go) * ftanh(ct));
            }
            gsync();
        }
        // flush c for decoder re-tiling
        for (int i = tid; i < BM * 32; i += 256) {
            int m = i >> 5, uu = i & 31;
            g_c[(size_t)(m0 + m) * H2 + dir * H + nt * 32 + uu] = cS[i];
        }
        gsync();
    }

    // =============== decoder ===============
    {
        int mt = bx >> 5, nt = bx & 31;
        int m0 = mt * BM, n0 = nt * BN;
        const __half* W = g_Wdec + (size_t)n0 * KDEC;

        for (int i = tid; i < BM * 32; i += 256) {
            int m = i >> 5, uu = i & 31;
            cS[i] = g_c[(size_t)(m0 + m) * H2 + nt * 32 + uu];
        }
        if (tid < BN) { sBias[tid] = g_bdec[n0 + tid]; sWin[tid] = g_win[n0 + tid]; }
        if (tid < 32) sFc[tid] = g_fcw[nt * 32 + tid];
        __syncthreads();

        for (int l = 0; l < L_OUT; l++) {
            int p = l & 1;
            const __half* hbase = g_h[p] + (size_t)m0 * H2;
            __half* hout = g_h[p ^ 1];

            float acc[2][4][4];
#pragma unroll
            for (int a = 0; a < 2; a++)
#pragma unroll
                for (int bq = 0; bq < 4; bq++)
#pragma unroll
                    for (int cq = 0; cq < 4; cq++) acc[a][bq][cq] = 0.0f;

#pragma unroll
            for (int s = 0; s < 2; s++) {
                load_chunk(dynu + (uint32_t)(s * STG_H) * 2u, hbase + s * KC, H2, 1,
                           W + s * KC, KDEC, tid);
                CP_COMMIT();
            }
            // overlap: previous prediction partials (deterministic order)
            {
                int r = tid >> 2, q = tid & 3;
                float s = 0.0f;
                if (l > 0) {
                    const float* dp = g_dpart + (size_t)(l - 1) * 32 * B + m0 + r;
#pragma unroll
                    for (int j = 0; j < 8; j++) s += dp[(q * 8 + j) * B];
                }
                predP[r][q] = s;
            }
            for (int ch = 0; ch < NCHD; ch++) {
                CP_WAIT1();
                __syncthreads();
                int pf = ch + 2;
                if (pf < NCHD)
                    load_chunk(dynu + (uint32_t)((pf % 3) * STG_H) * 2u, hbase + pf * KC, H2, 1,
                               W + pf * KC, KDEC, tid);
                CP_COMMIT();
                const __half* st = dyn + (ch % 3) * STG_H;
                mma_chunk(st, st + BM * PADH, acc, wm, wn, g, tg);
            }
            __syncthreads();
            if (tid < BM)
                predS[tid] = (l > 0)
                    ? (predP[tid][0] + predP[tid][1] + predP[tid][2] + predP[tid][3] + fcb0)
                    : 0.0f;
            store_gates(dynf, acc, wm, wn, g, tg);
            __syncthreads();
            float* Hs = dynf + BM * GSP;
            for (int i = tid; i < BM * 32; i += 256) {
                int m = i >> 5, uu = i & 31;
                float4 gv = *reinterpret_cast<const float4*>(dynf + m * GSP + 4 * uu);
                int nn = 4 * uu;
                float pb = predS[m];
                float gi = gv.x + sBias[nn]     + pb * sWin[nn];
                float gf = gv.y + sBias[nn + 1] + pb * sWin[nn + 1];
                float gg = gv.z + sBias[nn + 2] + pb * sWin[nn + 2];
                float go = gv.w + sBias[nn + 3] + pb * sWin[nn + 3];
                float ct = fsigm(gf) * cS[i] + fsigm(gi) * ftanh(gg);
                cS[i] = ct;
                float ht = fsigm(go) * ftanh(ct);
                hout[(size_t)(m0 + m) * H2 + nt * 32 + uu] = __float2half(ht);
                Hs[m * HSP + uu] = ht;
            }
            __syncthreads();
            if (tid < BM) {
                float s = 0.0f;
#pragma unroll
                for (int j = 0; j < 32; j++) s += sFc[j] * Hs[tid * HSP + j];
                g_dpart[(size_t)(l * 32 + nt) * B + m0 + tid] = s;
            }
            gsync();
        }
    }

    // =============== finalize ===============
    {
        int idx = bx * 256 + tid;
        if (idx < B * L_OUT) {
            int b = idx / L_OUT, l = idx - b * L_OUT;
            float s = fcb0;
#pragma unroll
            for (int j = 0; j < 32; j++) s += g_dpart[(size_t)(l * 32 + j) * B + b];
            out[idx] = s;
        }
    }
}

// ---------------- launch ----------------
extern "C" void kernel_launch(void* const* d_in, const int* in_sizes, int n_in,
                              void* d_out, int out_size) {
    const float* x      = (const float*)d_in[0];
    const float* eWih_f = (const float*)d_in[1];
    const float* eWhh_f = (const float*)d_in[2];
    const float* ebih_f = (const float*)d_in[3];
    const float* ebhh_f = (const float*)d_in[4];
    const float* eWih_b = (const float*)d_in[5];
    const float* eWhh_b = (const float*)d_in[6];
    const float* ebih_b = (const float*)d_in[7];
    const float* ebhh_b = (const float*)d_in[8];
    const float* dWih   = (const float*)d_in[9];
    const float* dWhh   = (const float*)d_in[10];
    const float* dbih   = (const float*)d_in[11];
    const float* dbhh   = (const float*)d_in[12];
    const float* fcW    = (const float*)d_in[13];
    const float* fcb    = (const float*)d_in[14];

    cudaFuncSetAttribute(persist, cudaFuncAttributeMaxDynamicSharedMemorySize, DYNB);

    prep_misc<<<(T * B * F_IN + 255) / 256, 256>>>(x);
    prep_w<<<(PREP_TOT + 255) / 256, 256>>>(eWih_f, eWhh_f, ebih_f, ebhh_f,
                                            eWih_b, eWhh_b, ebih_b, ebhh_b,
                                            dWih, dWhh, dbih, dbhh, fcW);
    persist<<<NCTA, 256, DYNB>>>((float*)d_out, fcb);
}

// round 9
// speedup vs baseline: 4.3343x; 1.5202x over previous
#include <cuda_runtime.h>
#include <cuda_fp16.h>
#include <cstdint>
#include <math.h>

// ---------------- problem constants ----------------
#define B      256
#define T      168
#define F_IN   128
#define H      512
#define H4     2048
#define KENC   640
#define H2     1024
#define NDEC   4096
#define KDEC   1024
#define L_OUT  48

// ---------------- tiling ----------------
#define BM     64
#define BN     128
#define KC     128
#define PADH   136                    // halves; row stride 272B -> conflict-free
#define GSP    132                    // gate buffer stride (floats)
#define HSP    33
#define STG_H  ((BM + BN) * PADH)     // 26112 halves / stage
#define STG_B  (STG_H * 2)            // 52224 bytes
#define GOFF   (3 * STG_B)            // gates byte offset in dyn
#define HOFF   (GOFF + BM * GSP * 4)
#define DYNB   (HOFF + BM * HSP * 4)  // 198912 bytes
#define NCTA   128
#define NCHE   5
#define NCHD   8

// ---------------- device scratch ----------------
__device__ __align__(16) __half g_xT[(size_t)T * B * F_IN];
__device__ __align__(16) __half g_Wenc[2][H4 * KENC];
__device__ __align__(16) float  g_benc[2][H4];
__device__ __align__(16) __half g_Wdec[(size_t)NDEC * KDEC];
__device__ __align__(16) float  g_bdec[NDEC];
__device__ __align__(16) float  g_win[NDEC];
__device__ __align__(16) float  g_fcw[H2];
__device__ __align__(16) __half g_h[2][B * H2];
__device__ __align__(16) float  g_c[B * H2];
__device__ __align__(16) float  g_dpart[L_OUT * 32 * B];

__device__ unsigned g_bcnt[16];
__device__ unsigned g_bgen[16];

// ---------------- helpers ----------------
__device__ __forceinline__ float fsigm(float x) { return __fdividef(1.0f, 1.0f + __expf(-x)); }
__device__ __forceinline__ float ftanh(float x) { return __fdividef(2.0f, 1.0f + __expf(-2.0f * x)) - 1.0f; }
__device__ __forceinline__ float ldcg(const float* p) {
    float v; asm volatile("ld.global.cg.f32 %0, [%1];" : "=f"(v) : "l"(p)); return v;
}

// group barrier: tid0 release-arrival + acquire-spin; cross-CTA reads use .cg
__device__ __forceinline__ void barrier_grp(int g, unsigned n) {
    __syncthreads();
    if (threadIdx.x == 0) {
        unsigned cur, old;
        asm volatile("ld.relaxed.gpu.global.u32 %0, [%1];" : "=r"(cur) : "l"(&g_bgen[g]));
        asm volatile("atom.acq_rel.gpu.global.add.u32 %0, [%1], 1;" : "=r"(old) : "l"(&g_bcnt[g]));
        if (old == n - 1u) {
            asm volatile("st.relaxed.gpu.global.u32 [%0], %1;" :: "l"(&g_bcnt[g]), "r"(0u));
            asm volatile("st.release.gpu.global.u32 [%0], %1;" :: "l"(&g_bgen[g]), "r"(cur + 1u));
        } else {
            unsigned v;
            do {
                asm volatile("ld.acquire.gpu.global.u32 %0, [%1];" : "=r"(v) : "l"(&g_bgen[g]));
            } while (v == cur);
        }
    }
    __syncthreads();
}

__device__ __forceinline__ void cpa16_ca(uint32_t dst, const __half* src) {
    asm volatile("cp.async.ca.shared.global [%0], [%1], 16;\n" :: "r"(dst), "l"(src));
}
__device__ __forceinline__ void cpa16_cg(uint32_t dst, const __half* src) {
    asm volatile("cp.async.cg.shared.global [%0], [%1], 16;\n" :: "r"(dst), "l"(src));
}
#define CP_COMMIT() asm volatile("cp.async.commit_group;\n" ::: "memory")
#define CP_WAIT1()  asm volatile("cp.async.wait_group 1;\n" ::: "memory")

// A-part of a stage (BM x KC halves)
__device__ __forceinline__ void load_A(uint32_t su, const __half* __restrict__ a,
                                       int astride, int tid, int cg) {
#pragma unroll
    for (int i = tid; i < BM * 16; i += 256) {
        int r = i >> 4, v = i & 15;
        uint32_t d = su + (uint32_t)(r * PADH + v * 8) * 2u;
        const __half* s = a + (size_t)r * astride + v * 8;
        if (cg) cpa16_cg(d, s); else cpa16_ca(d, s);
    }
}
// B-part of a stage (BN x KC halves)
__device__ __forceinline__ void load_B(uint32_t su, const __half* __restrict__ b,
                                       int bstride, int tid) {
    uint32_t bu = su + (uint32_t)(BM * PADH) * 2u;
#pragma unroll
    for (int i = tid; i < BN * 16; i += 256) {
        int r = i >> 4, v = i & 15;
        cpa16_ca(bu + (uint32_t)(r * PADH + v * 8) * 2u, b + (size_t)r * bstride + v * 8);
    }
}

// ---------------- ldmatrix + mma ----------------
__device__ __forceinline__ void lm4(uint32_t (&r)[4], uint32_t addr) {
    asm volatile("ldmatrix.sync.aligned.m8n8.x4.shared.b16 {%0,%1,%2,%3}, [%4];"
                 : "=r"(r[0]), "=r"(r[1]), "=r"(r[2]), "=r"(r[3]) : "r"(addr));
}
__device__ __forceinline__ void hmma(float (&d)[4], const uint32_t (&a)[4],
                                     uint32_t b0, uint32_t b1) {
    asm volatile("mma.sync.aligned.m16n8k16.row.col.f32.f16.f16.f32 "
                 "{%0,%1,%2,%3},{%4,%5,%6,%7},{%8,%9},{%0,%1,%2,%3};"
                 : "+f"(d[0]), "+f"(d[1]), "+f"(d[2]), "+f"(d[3])
                 : "r"(a[0]), "r"(a[1]), "r"(a[2]), "r"(a[3]), "r"(b0), "r"(b1));
}
// one KC=128 chunk: 8 k16-blocks x (4 ldmatrix.x4 + 8 HMMA)
__device__ __forceinline__ void mma_chunk_lm(uint32_t su, float (&acc)[2][4][4],
                                             uint32_t bA0, uint32_t bA1,
                                             uint32_t bB0, uint32_t bB1) {
#pragma unroll
    for (int kb = 0; kb < 8; kb++) {
        uint32_t ko = su + (uint32_t)kb * 32u;
        uint32_t a0[4], a1[4], b0[4], b1[4];
        lm4(a0, ko + bA0);
        lm4(a1, ko + bA1);
        lm4(b0, ko + bB0);
        lm4(b1, ko + bB1);
        hmma(acc[0][0], a0, b0[0], b0[2]);
        hmma(acc[0][1], a0, b0[1], b0[3]);
        hmma(acc[0][2], a0, b1[0], b1[2]);
        hmma(acc[0][3], a0, b1[1], b1[3]);
        hmma(acc[1][0], a1, b0[0], b0[2]);
        hmma(acc[1][1], a1, b0[1], b0[3]);
        hmma(acc[1][2], a1, b1[0], b1[2]);
        hmma(acc[1][3], a1, b1[1], b1[3]);
    }
}

__device__ __forceinline__ void store_gates(float* __restrict__ Gs,
                                            float (&acc)[2][4][4],
                                            int wm, int wn, int g, int tg) {
#pragma unroll
    for (int mi = 0; mi < 2; mi++)
#pragma unroll
        for (int ni = 0; ni < 4; ni++) {
            int row = wm * 32 + mi * 16 + g;
            int col = wn * 32 + ni * 8 + 2 * tg;
            Gs[row * GSP + col]           = acc[mi][ni][0];
            Gs[row * GSP + col + 1]       = acc[mi][ni][1];
            Gs[(row + 8) * GSP + col]     = acc[mi][ni][2];
            Gs[(row + 8) * GSP + col + 1] = acc[mi][ni][3];
        }
}

// ---------------- prep ----------------
__global__ void prep_misc(const float* __restrict__ x) {
    int i = blockIdx.x * blockDim.x + threadIdx.x;
    if (i < T * B * F_IN) {
        int f = i & 127;
        int r = i >> 7;
        int b = r & 255;
        int t = r >> 8;
        g_xT[i] = __float2half(x[((size_t)b * T + t) * F_IN + f]);
    }
    if (i < B * H2) {
        g_h[0][i] = __half(0.0f);
        g_h[1][i] = __half(0.0f);
    }
}

#define EW (2 * H4 * KENC)
#define DW (NDEC * KDEC)
#define PREP_TOT (EW + DW + 2 * H4 + NDEC + H2)

__global__ void prep_w(const float* __restrict__ eWih_f, const float* __restrict__ eWhh_f,
                       const float* __restrict__ ebih_f, const float* __restrict__ ebhh_f,
                       const float* __restrict__ eWih_b, const float* __restrict__ eWhh_b,
                       const float* __restrict__ ebih_b, const float* __restrict__ ebhh_b,
                       const float* __restrict__ dWih,   const float* __restrict__ dWhh,
                       const float* __restrict__ dbih,   const float* __restrict__ dbhh,
                       const float* __restrict__ fcW) {
    int i = blockIdx.x * blockDim.x + threadIdx.x;
    if (i >= PREP_TOT) return;

    if (i < EW) {
        int dir = i / (H4 * KENC);
        int r   = i - dir * (H4 * KENC);
        int n   = r / KENC;
        int k   = r - n * KENC;
        int u = n >> 2, gt = n & 3;
        int row = gt * H + u;
        const float* Wih = dir ? eWih_b : eWih_f;
        const float* Whh = dir ? eWhh_b : eWhh_f;
        float v = (k < F_IN) ? Wih[row * F_IN + k] : Whh[row * H + (k - F_IN)];
        g_Wenc[dir][n * KENC + k] = __float2half(v);
    } else if (i < EW + DW) {
        int r = i - EW;
        int n = r / KDEC;
        int k = r - n * KDEC;
        int u = n >> 2, gt = n & 3;
        int row = gt * H2 + u;
        g_Wdec[(size_t)n * KDEC + k] = __float2half(dWhh[(size_t)row * KDEC + k]);
    } else {
        int r = i - EW - DW;
        if (r < 2 * H4) {
            int dir = r >> 11;
            int n = r & (H4 - 1);
            int u = n >> 2, gt = n & 3;
            int row = gt * H + u;
            g_benc[dir][n] = dir ? (ebih_b[row] + ebhh_b[row]) : (ebih_f[row] + ebhh_f[row]);
        } else if (r < 2 * H4 + NDEC) {
            int n = r - 2 * H4;
            int u = n >> 2, gt = n & 3;
            int row = gt * H2 + u;
            g_bdec[n] = dbih[row] + dbhh[row];
            g_win[n]  = dWih[row];
        } else {
            int u = r - 2 * H4 - NDEC;
            g_fcw[u] = fcW[u];
        }
    }
}

// ---------------- persistent kernel ----------------
__global__ __launch_bounds__(256, 1) void persist(float* __restrict__ out,
                                                  const float* __restrict__ fcb) {
    extern __shared__ __align__(16) unsigned char dynraw[];
    __half* dynh = reinterpret_cast<__half*>(dynraw);
    float*  gS   = reinterpret_cast<float*>(dynraw + GOFF);
    float*  Hs   = reinterpret_cast<float*>(dynraw + HOFF);
    __shared__ float cS[BM * 32];
    __shared__ float sBias[BN];
    __shared__ float sWin[BN];
    __shared__ float sFc[32];
    __shared__ float predS[BM];
    __shared__ float predP[BM][4];

    uint32_t dynu = (uint32_t)__cvta_generic_to_shared(dynh);
    int bx = blockIdx.x;
    int tid = threadIdx.x;
    int lane = tid & 31, wid = tid >> 5;
    int wm = wid & 1, wn = wid >> 1;
    int g = lane >> 2, tg = lane & 3;
    int la15 = lane & 15, lk = (lane >> 4) << 3;
    float fcb0 = fcb[0];

    // ldmatrix base addresses (byte offsets within a stage)
    uint32_t bA0 = (uint32_t)((wm * 32 + 0 * 16 + la15) * PADH + lk) * 2u;
    uint32_t bA1 = (uint32_t)((wm * 32 + 1 * 16 + la15) * PADH + lk) * 2u;
    uint32_t bB0 = (uint32_t)((BM + wn * 32 + 0 * 16 + la15) * PADH + lk) * 2u;
    uint32_t bB1 = (uint32_t)((BM + wn * 32 + 1 * 16 + la15) * PADH + lk) * 2u;

    // =============== encoder ===============
    {
        int dir = bx >> 6;
        int mt  = (bx >> 4) & 3;
        int nt  = bx & 15;
        int gid = bx >> 4;                    // 8 groups of 16 CTAs
        int m0 = mt * BM, n0 = nt * BN;
        const __half* W = g_Wenc[dir] + (size_t)n0 * KENC;

        for (int i = tid; i < BM * 32; i += 256) cS[i] = 0.0f;
        if (tid < BN) sBias[tid] = g_benc[dir][n0 + tid];
        __syncthreads();

        // prologue: C0 (x(t=0) + W0), B1 (W1)
        {
            int tt0 = dir ? (T - 1) : 0;
            load_A(dynu, g_xT + ((size_t)tt0 * B + m0) * F_IN, F_IN, tid, 0);
            load_B(dynu, W, KENC, tid);
            CP_COMMIT();
            load_B(dynu + (uint32_t)STG_B, W + KC, KENC, tid);
            CP_COMMIT();
        }

        int st0 = 0;
        for (int t = 0; t < T; t++) {
            int p = t & 1;
            const __half* hb = g_h[p] + (size_t)m0 * H2 + dir * H;
            __half* hout = g_h[p ^ 1];

            // A-part of chunk1 (h cols 0..KC)
            load_A(dynu + (uint32_t)(((st0 + 1) % 3) * STG_B), hb, H2, tid, 1);
            CP_COMMIT();

            float acc[2][4][4];
#pragma unroll
            for (int a = 0; a < 2; a++)
#pragma unroll
                for (int bq = 0; bq < 4; bq++)
#pragma unroll
                    for (int cq = 0; cq < 4; cq++) acc[a][bq][cq] = 0.0f;

#pragma unroll
            for (int ch = 0; ch < NCHE; ch++) {
                CP_WAIT1();
                __syncthreads();
                int pf = ch + 2;
                if (pf <= 4) {
                    uint32_t su = dynu + (uint32_t)(((st0 + pf) % 3) * STG_B);
                    load_A(su, hb + (pf * KC - F_IN), H2, tid, 1);
                    load_B(su, W + pf * KC, KENC, tid);
                } else if (pf == 5 && t + 1 < T) {
                    // next step chunk0: x(t+1) + W0  (h-independent -> pre-barrier)
                    int tt2 = dir ? (T - 2 - t) : (t + 1);
                    uint32_t su = dynu + (uint32_t)(((st0 + 2) % 3) * STG_B);
                    load_A(su, g_xT + ((size_t)tt2 * B + m0) * F_IN, F_IN, tid, 0);
                    load_B(su, W, KENC, tid);
                } else if (pf == 6 && t + 1 < T) {
                    // next step chunk1 W-part
                    load_B(dynu + (uint32_t)((st0 % 3) * STG_B), W + KC, KENC, tid);
                }
                CP_COMMIT();
                mma_chunk_lm(dynu + (uint32_t)(((st0 + ch) % 3) * STG_B), acc,
                             bA0, bA1, bB0, bB1);
            }

            store_gates(gS, acc, wm, wn, g, tg);
            __syncthreads();
            for (int i = tid; i < BM * 32; i += 256) {
                int m = i >> 5, uu = i & 31;
                float4 gv = *reinterpret_cast<const float4*>(gS + m * GSP + 4 * uu);
                int nn = 4 * uu;
                float gi = gv.x + sBias[nn];
                float gf = gv.y + sBias[nn + 1];
                float gg = gv.z + sBias[nn + 2];
                float go = gv.w + sBias[nn + 3];
                float ct = fsigm(gf) * cS[i] + fsigm(gi) * ftanh(gg);
                cS[i] = ct;
                hout[(size_t)(m0 + m) * H2 + dir * H + nt * 32 + uu] =
                    __float2half(fsigm(go) * ftanh(ct));
            }
            barrier_grp(gid, 16);
            st0 = (st0 + 2) % 3;
        }

        // flush c for decoder re-tiling
        for (int i = tid; i < BM * 32; i += 256) {
            int m = i >> 5, uu = i & 31;
            g_c[(size_t)(m0 + m) * H2 + dir * H + nt * 32 + uu] = cS[i];
        }
        barrier_grp(12, NCTA);   // full transition barrier
    }

    // =============== decoder ===============
    {
        int mt = bx >> 5, nt = bx & 31;
        int gid = 8 + mt;                     // 4 groups of 32 CTAs
        int m0 = mt * BM, n0 = nt * BN;
        const __half* W = g_Wdec + (size_t)n0 * KDEC;

        // prologue: W-parts of chunks 0/1 (h-independent)
        load_B(dynu, W, KDEC, tid);
        CP_COMMIT();
        load_B(dynu + (uint32_t)STG_B, W + KC, KDEC, tid);
        CP_COMMIT();

        for (int i = tid; i < BM * 32; i += 256) {
            int m = i >> 5, uu = i & 31;
            cS[i] = ldcg(&g_c[(size_t)(m0 + m) * H2 + nt * 32 + uu]);
        }
        if (tid < BN) { sBias[tid] = g_bdec[n0 + tid]; sWin[tid] = g_win[n0 + tid]; }
        if (tid < 32) sFc[tid] = g_fcw[nt * 32 + tid];
        __syncthreads();

        int st0 = 0;
        for (int l = 0; l < L_OUT; l++) {
            int p = l & 1;
            const __half* hbase = g_h[p] + (size_t)m0 * H2;
            __half* hout = g_h[p ^ 1];

            load_A(dynu + (uint32_t)((st0 % 3) * STG_B), hbase, H2, tid, 1);
            CP_COMMIT();
            load_A(dynu + (uint32_t)(((st0 + 1) % 3) * STG_B), hbase + KC, H2, tid, 1);
            CP_COMMIT();

            // previous prediction partials (L1-bypass; barrier ordered)
            {
                int r = tid >> 2, q = tid & 3;
                float s = 0.0f;
                if (l > 0) {
                    const float* dp = g_dpart + (size_t)(l - 1) * 32 * B + m0 + r;
#pragma unroll
                    for (int j = 0; j < 8; j++) s += ldcg(dp + (q * 8 + j) * B);
                }
                predP[r][q] = s;
            }

            float acc[2][4][4];
#pragma unroll
            for (int a = 0; a < 2; a++)
#pragma unroll
                for (int bq = 0; bq < 4; bq++)
#pragma unroll
                    for (int cq = 0; cq < 4; cq++) acc[a][bq][cq] = 0.0f;

#pragma unroll
            for (int ch = 0; ch < NCHD; ch++) {
                CP_WAIT1();
                __syncthreads();
                int pf = ch + 2;
                if (pf <= 7) {
                    uint32_t su = dynu + (uint32_t)(((st0 + pf) % 3) * STG_B);
                    load_A(su, hbase + pf * KC, H2, tid, 1);
                    load_B(su, W + pf * KC, KDEC, tid);
                } else if (pf == 8 && l + 1 < L_OUT) {
                    load_B(dynu + (uint32_t)(((st0 + 2) % 3) * STG_B), W, KDEC, tid);
                } else if (pf == 9 && l + 1 < L_OUT) {
                    load_B(dynu + (uint32_t)((st0 % 3) * STG_B), W + KC, KDEC, tid);
                }
                CP_COMMIT();
                mma_chunk_lm(dynu + (uint32_t)(((st0 + ch) % 3) * STG_B), acc,
                             bA0, bA1, bB0, bB1);
            }

            if (tid < BM)
                predS[tid] = (l > 0)
                    ? (predP[tid][0] + predP[tid][1] + predP[tid][2] + predP[tid][3] + fcb0)
                    : 0.0f;
            store_gates(gS, acc, wm, wn, g, tg);
            __syncthreads();
            for (int i = tid; i < BM * 32; i += 256) {
                int m = i >> 5, uu = i & 31;
                float4 gv = *reinterpret_cast<const float4*>(gS + m * GSP + 4 * uu);
                int nn = 4 * uu;
                float pb = predS[m];
                float gi = gv.x + sBias[nn]     + pb * sWin[nn];
                float gf = gv.y + sBias[nn + 1] + pb * sWin[nn + 1];
                float gg = gv.z + sBias[nn + 2] + pb * sWin[nn + 2];
                float go = gv.w + sBias[nn + 3] + pb * sWin[nn + 3];
                float ct = fsigm(gf) * cS[i] + fsigm(gi) * ftanh(gg);
                cS[i] = ct;
                float ht = fsigm(go) * ftanh(ct);
                hout[(size_t)(m0 + m) * H2 + nt * 32 + uu] = __float2half(ht);
                Hs[m * HSP + uu] = ht;
            }
            __syncthreads();
            if (tid < BM) {
                float s = 0.0f;
#pragma unroll
                for (int j = 0; j < 32; j++) s += sFc[j] * Hs[tid * HSP + j];
                g_dpart[(size_t)(l * 32 + nt) * B + m0 + tid] = s;
            }
            barrier_grp(gid, 32);
            st0 = (st0 + 2) % 3;
        }
    }

    // =============== finalize (after full barrier) ===============
    barrier_grp(13, NCTA);
    {
        int idx = bx * 256 + tid;
        if (idx < B * L_OUT) {
            int b = idx / L_OUT, l = idx - b * L_OUT;
            float s = fcb0;
#pragma unroll
            for (int j = 0; j < 32; j++) s += ldcg(&g_dpart[(size_t)(l * 32 + j) * B + b]);
            out[idx] = s;
        }
    }
}

// ---------------- launch ----------------
extern "C" void kernel_launch(void* const* d_in, const int* in_sizes, int n_in,
                              void* d_out, int out_size) {
    const float* x      = (const float*)d_in[0];
    const float* eWih_f = (const float*)d_in[1];
    const float* eWhh_f = (const float*)d_in[2];
    const float* ebih_f = (const float*)d_in[3];
    const float* ebhh_f = (const float*)d_in[4];
    const float* eWih_b = (const float*)d_in[5];
    const float* eWhh_b = (const float*)d_in[6];
    const float* ebih_b = (const float*)d_in[7];
    const float* ebhh_b = (const float*)d_in[8];
    const float* dWih   = (const float*)d_in[9];
    const float* dWhh   = (const float*)d_in[10];
    const float* dbih   = (const float*)d_in[11];
    const float* dbhh   = (const float*)d_in[12];
    const float* fcW    = (const float*)d_in[13];
    const float* fcb    = (const float*)d_in[14];

    cudaFuncSetAttribute(persist, cudaFuncAttributeMaxDynamicSharedMemorySize, DYNB);

    prep_misc<<<(T * B * F_IN + 255) / 256, 256>>>(x);
    prep_w<<<(PREP_TOT + 255) / 256, 256>>>(eWih_f, eWhh_f, ebih_f, ebhh_f,
                                            eWih_b, eWhh_b, ebih_b, ebhh_b,
                                            dWih, dWhh, dbih, dbhh, fcW);
    persist<<<NCTA, 256, DYNB>>>((float*)d_out, fcb);
}

// round 10
// speedup vs baseline: 4.3544x; 1.0046x over previous
#include <cuda_runtime.h>
#include <cuda_fp16.h>
#include <cstdint>
#include <math.h>

// ---------------- problem constants ----------------
#define B      256
#define T      168
#define F_IN   128
#define H      512
#define H4     2048
#define KENC   640
#define H2     1024
#define NDEC   4096
#define KDEC   1024
#define L_OUT  48

// ---------------- tiling ----------------
#define BM     64
#define BN     128
#define KC     128
#define PADH   136                    // halves; row stride 272B -> conflict-free
#define GSP    132                    // gate buffer stride (floats)
#define HSP    33
#define STG_H  ((BM + BN) * PADH)     // 26112 halves / stage
#define STG_B  (STG_H * 2)            // 52224 bytes
#define GOFF   (3 * STG_B)            // gates byte offset in dyn
#define HOFF   (GOFF + BM * GSP * 4)
#define DYNB   (HOFF + BM * HSP * 4)  // 198912 bytes
#define NCTA   128
#define NCHE   5
#define NCHD   8

// ---------------- device scratch ----------------
__device__ __align__(16) __half g_xT[(size_t)T * B * F_IN];
__device__ __align__(16) __half g_Wenc[2][H4 * KENC];
__device__ __align__(16) float  g_benc[2][H4];
__device__ __align__(16) __half g_Wdec[(size_t)NDEC * KDEC];
__device__ __align__(16) float  g_bdec[NDEC];
__device__ __align__(16) float  g_win[NDEC];
__device__ __align__(16) float  g_fcw[H2];
__device__ __align__(16) __half g_h[2][B * H2];
__device__ __align__(16) float  g_c[B * H2];
__device__ __align__(16) float  g_dpart[L_OUT * 32 * B];

__device__ unsigned g_bcnt[16];
__device__ unsigned g_bgen[16];

// ---------------- helpers ----------------
__device__ __forceinline__ float fsigm(float x) { return __fdividef(1.0f, 1.0f + __expf(-x)); }
__device__ __forceinline__ float ftanh(float x) { return __fdividef(2.0f, 1.0f + __expf(-2.0f * x)) - 1.0f; }
__device__ __forceinline__ float ldcg(const float* p) {
    float v; asm volatile("ld.global.cg.f32 %0, [%1];" : "=f"(v) : "l"(p)); return v;
}

// group barrier: tid0 release-arrival + acquire-spin; cross-CTA reads use .cg
__device__ __forceinline__ void barrier_grp(int g, unsigned n) {
    __syncthreads();
    if (threadIdx.x == 0) {
        unsigned cur, old;
        asm volatile("ld.relaxed.gpu.global.u32 %0, [%1];" : "=r"(cur) : "l"(&g_bgen[g]));
        asm volatile("atom.acq_rel.gpu.global.add.u32 %0, [%1], 1;" : "=r"(old) : "l"(&g_bcnt[g]));
        if (old == n - 1u) {
            asm volatile("st.relaxed.gpu.global.u32 [%0], %1;" :: "l"(&g_bcnt[g]), "r"(0u));
            asm volatile("st.release.gpu.global.u32 [%0], %1;" :: "l"(&g_bgen[g]), "r"(cur + 1u));
        } else {
            unsigned v;
            do {
                asm volatile("ld.acquire.gpu.global.u32 %0, [%1];" : "=r"(v) : "l"(&g_bgen[g]));
            } while (v == cur);
        }
    }
    __syncthreads();
}

__device__ __forceinline__ void cpa16_ca(uint32_t dst, const __half* src) {
    asm volatile("cp.async.ca.shared.global [%0], [%1], 16;\n" :: "r"(dst), "l"(src));
}
__device__ __forceinline__ void cpa16_cg(uint32_t dst, const __half* src) {
    asm volatile("cp.async.cg.shared.global [%0], [%1], 16;\n" :: "r"(dst), "l"(src));
}
#define CP_COMMIT() asm volatile("cp.async.commit_group;\n" ::: "memory")
#define CP_WAIT1()  asm volatile("cp.async.wait_group 1;\n" ::: "memory")

// A-part of a stage (BM x KC halves)
__device__ __forceinline__ void load_A(uint32_t su, const __half* __restrict__ a,
                                       int astride, int tid, int cg) {
#pragma unroll
    for (int i = tid; i < BM * 16; i += 256) {
        int r = i >> 4, v = i & 15;
        uint32_t d = su + (uint32_t)(r * PADH + v * 8) * 2u;
        const __half* s = a + (size_t)r * astride + v * 8;
        if (cg) cpa16_cg(d, s); else cpa16_ca(d, s);
    }
}
// B-part of a stage (BN x KC halves)
__device__ __forceinline__ void load_B(uint32_t su, const __half* __restrict__ b,
                                       int bstride, int tid) {
    uint32_t bu = su + (uint32_t)(BM * PADH) * 2u;
#pragma unroll
    for (int i = tid; i < BN * 16; i += 256) {
        int r = i >> 4, v = i & 15;
        cpa16_ca(bu + (uint32_t)(r * PADH + v * 8) * 2u, b + (size_t)r * bstride + v * 8);
    }
}

// ---------------- ldmatrix + mma ----------------
__device__ __forceinline__ void lm4(uint32_t (&r)[4], uint32_t addr) {
    asm volatile("ldmatrix.sync.aligned.m8n8.x4.shared.b16 {%0,%1,%2,%3}, [%4];"
                 : "=r"(r[0]), "=r"(r[1]), "=r"(r[2]), "=r"(r[3]) : "r"(addr));
}
__device__ __forceinline__ void hmma(float (&d)[4], const uint32_t (&a)[4],
                                     uint32_t b0, uint32_t b1) {
    asm volatile("mma.sync.aligned.m16n8k16.row.col.f32.f16.f16.f32 "
                 "{%0,%1,%2,%3},{%4,%5,%6,%7},{%8,%9},{%0,%1,%2,%3};"
                 : "+f"(d[0]), "+f"(d[1]), "+f"(d[2]), "+f"(d[3])
                 : "r"(a[0]), "r"(a[1]), "r"(a[2]), "r"(a[3]), "r"(b0), "r"(b1));
}
// one KC=128 chunk: 8 k16-blocks x (4 ldmatrix.x4 + 8 HMMA)
__device__ __forceinline__ void mma_chunk_lm(uint32_t su, float (&acc)[2][4][4],
                                             uint32_t bA0, uint32_t bA1,
                                             uint32_t bB0, uint32_t bB1) {
#pragma unroll
    for (int kb = 0; kb < 8; kb++) {
        uint32_t ko = su + (uint32_t)kb * 32u;
        uint32_t a0[4], a1[4], b0[4], b1[4];
        lm4(a0, ko + bA0);
        lm4(a1, ko + bA1);
        lm4(b0, ko + bB0);
        lm4(b1, ko + bB1);
        hmma(acc[0][0], a0, b0[0], b0[2]);
        hmma(acc[0][1], a0, b0[1], b0[3]);
        hmma(acc[0][2], a0, b1[0], b1[2]);
        hmma(acc[0][3], a0, b1[1], b1[3]);
        hmma(acc[1][0], a1, b0[0], b0[2]);
        hmma(acc[1][1], a1, b0[1], b0[3]);
        hmma(acc[1][2], a1, b1[0], b1[2]);
        hmma(acc[1][3], a1, b1[1], b1[3]);
    }
}

__device__ __forceinline__ void store_gates(float* __restrict__ Gs,
                                            float (&acc)[2][4][4],
                                            int wm, int wn, int g, int tg) {
#pragma unroll
    for (int mi = 0; mi < 2; mi++)
#pragma unroll
        for (int ni = 0; ni < 4; ni++) {
            int row = wm * 32 + mi * 16 + g;
            int col = wn * 32 + ni * 8 + 2 * tg;
            Gs[row * GSP + col]           = acc[mi][ni][0];
            Gs[row * GSP + col + 1]       = acc[mi][ni][1];
            Gs[(row + 8) * GSP + col]     = acc[mi][ni][2];
            Gs[(row + 8) * GSP + col + 1] = acc[mi][ni][3];
        }
}

// ---------------- prep ----------------
__global__ void prep_misc(const float* __restrict__ x) {
    int i = blockIdx.x * blockDim.x + threadIdx.x;
    if (i < T * B * F_IN) {
        int f = i & 127;
        int r = i >> 7;
        int b = r & 255;
        int t = r >> 8;
        g_xT[i] = __float2half(x[((size_t)b * T + t) * F_IN + f]);
    }
    if (i < B * H2) {
        g_h[0][i] = __half(0.0f);
        g_h[1][i] = __half(0.0f);
    }
}

#define EW (2 * H4 * KENC)
#define DW (NDEC * KDEC)
#define PREP_TOT (EW + DW + 2 * H4 + NDEC + H2)

__global__ void prep_w(const float* __restrict__ eWih_f, const float* __restrict__ eWhh_f,
                       const float* __restrict__ ebih_f, const float* __restrict__ ebhh_f,
                       const float* __restrict__ eWih_b, const float* __restrict__ eWhh_b,
                       const float* __restrict__ ebih_b, const float* __restrict__ ebhh_b,
                       const float* __restrict__ dWih,   const float* __restrict__ dWhh,
                       const float* __restrict__ dbih,   const float* __restrict__ dbhh,
                       const float* __restrict__ fcW) {
    int i = blockIdx.x * blockDim.x + threadIdx.x;
    if (i >= PREP_TOT) return;

    if (i < EW) {
        int dir = i / (H4 * KENC);
        int r   = i - dir * (H4 * KENC);
        int n   = r / KENC;
        int k   = r - n * KENC;
        int u = n >> 2, gt = n & 3;
        int row = gt * H + u;
        const float* Wih = dir ? eWih_b : eWih_f;
        const float* Whh = dir ? eWhh_b : eWhh_f;
        float v = (k < F_IN) ? Wih[row * F_IN + k] : Whh[row * H + (k - F_IN)];
        g_Wenc[dir][n * KENC + k] = __float2half(v);
    } else if (i < EW + DW) {
        int r = i - EW;
        int n = r / KDEC;
        int k = r - n * KDEC;
        int u = n >> 2, gt = n & 3;
        int row = gt * H2 + u;
        g_Wdec[(size_t)n * KDEC + k] = __float2half(dWhh[(size_t)row * KDEC + k]);
    } else {
        int r = i - EW - DW;
        if (r < 2 * H4) {
            int dir = r >> 11;
            int n = r & (H4 - 1);
            int u = n >> 2, gt = n & 3;
            int row = gt * H + u;
            g_benc[dir][n] = dir ? (ebih_b[row] + ebhh_b[row]) : (ebih_f[row] + ebhh_f[row]);
        } else if (r < 2 * H4 + NDEC) {
            int n = r - 2 * H4;
            int u = n >> 2, gt = n & 3;
            int row = gt * H2 + u;
            g_bdec[n] = dbih[row] + dbhh[row];
            g_win[n]  = dWih[row];
        } else {
            int u = r - 2 * H4 - NDEC;
            g_fcw[u] = fcW[u];
        }
    }
}

// ---------------- persistent kernel ----------------
__global__ __launch_bounds__(256, 1) void persist(float* __restrict__ out,
                                                  const float* __restrict__ fcb) {
    extern __shared__ __align__(16) unsigned char dynraw[];
    __half* dynh = reinterpret_cast<__half*>(dynraw);
    float*  gS   = reinterpret_cast<float*>(dynraw + GOFF);
    float*  Hs   = reinterpret_cast<float*>(dynraw + HOFF);
    __shared__ float cS[BM * 32];
    __shared__ float sBias[BN];
    __shared__ float sWin[BN];
    __shared__ float sFc[32];
    __shared__ float predS[BM];
    __shared__ float predP[BM][4];

    uint32_t dynu = (uint32_t)__cvta_generic_to_shared(dynh);
    int bx = blockIdx.x;
    int tid = threadIdx.x;
    int lane = tid & 31, wid = tid >> 5;
    int wm = wid & 1, wn = wid >> 1;
    int g = lane >> 2, tg = lane & 3;
    int la15 = lane & 15, lk = (lane >> 4) << 3;
    float fcb0 = fcb[0];

    // ldmatrix base addresses (byte offsets within a stage)
    uint32_t bA0 = (uint32_t)((wm * 32 + 0 * 16 + la15) * PADH + lk) * 2u;
    uint32_t bA1 = (uint32_t)((wm * 32 + 1 * 16 + la15) * PADH + lk) * 2u;
    uint32_t bB0 = (uint32_t)((BM + wn * 32 + 0 * 16 + la15) * PADH + lk) * 2u;
    uint32_t bB1 = (uint32_t)((BM + wn * 32 + 1 * 16 + la15) * PADH + lk) * 2u;

    // =============== encoder ===============
    {
        int dir = bx >> 6;
        int mt  = (bx >> 4) & 3;
        int nt  = bx & 15;
        int gid = bx >> 4;                    // 8 groups of 16 CTAs
        int m0 = mt * BM, n0 = nt * BN;
        const __half* W = g_Wenc[dir] + (size_t)n0 * KENC;

        for (int i = tid; i < BM * 32; i += 256) cS[i] = 0.0f;
        if (tid < BN) sBias[tid] = g_benc[dir][n0 + tid];
        __syncthreads();

        // prologue: C0 (x(t=0) + W0), B1 (W1)
        {
            int tt0 = dir ? (T - 1) : 0;
            load_A(dynu, g_xT + ((size_t)tt0 * B + m0) * F_IN, F_IN, tid, 0);
            load_B(dynu, W, KENC, tid);
            CP_COMMIT();
            load_B(dynu + (uint32_t)STG_B, W + KC, KENC, tid);
            CP_COMMIT();
        }

        int st0 = 0;
        for (int t = 0; t < T; t++) {
            int p = t & 1;
            const __half* hb = g_h[p] + (size_t)m0 * H2 + dir * H;
            __half* hout = g_h[p ^ 1];

            // A-part of chunk1 (h cols 0..KC)
            load_A(dynu + (uint32_t)(((st0 + 1) % 3) * STG_B), hb, H2, tid, 1);
            CP_COMMIT();

            float acc[2][4][4];
#pragma unroll
            for (int a = 0; a < 2; a++)
#pragma unroll
                for (int bq = 0; bq < 4; bq++)
#pragma unroll
                    for (int cq = 0; cq < 4; cq++) acc[a][bq][cq] = 0.0f;

#pragma unroll
            for (int ch = 0; ch < NCHE; ch++) {
                CP_WAIT1();
                __syncthreads();
                int pf = ch + 2;
                if (pf <= 4) {
                    uint32_t su = dynu + (uint32_t)(((st0 + pf) % 3) * STG_B);
                    load_A(su, hb + (pf * KC - F_IN), H2, tid, 1);
                    load_B(su, W + pf * KC, KENC, tid);
                } else if (pf == 5 && t + 1 < T) {
                    // next step chunk0: x(t+1) + W0  (h-independent -> pre-barrier)
                    int tt2 = dir ? (T - 2 - t) : (t + 1);
                    uint32_t su = dynu + (uint32_t)(((st0 + 2) % 3) * STG_B);
                    load_A(su, g_xT + ((size_t)tt2 * B + m0) * F_IN, F_IN, tid, 0);
                    load_B(su, W, KENC, tid);
                } else if (pf == 6 && t + 1 < T) {
                    // next step chunk1 W-part
                    load_B(dynu + (uint32_t)((st0 % 3) * STG_B), W + KC, KENC, tid);
                }
                CP_COMMIT();
                mma_chunk_lm(dynu + (uint32_t)(((st0 + ch) % 3) * STG_B), acc,
                             bA0, bA1, bB0, bB1);
            }

            store_gates(gS, acc, wm, wn, g, tg);
            __syncthreads();
            for (int i = tid; i < BM * 32; i += 256) {
                int m = i >> 5, uu = i & 31;
                float4 gv = *reinterpret_cast<const float4*>(gS + m * GSP + 4 * uu);
                int nn = 4 * uu;
                float gi = gv.x + sBias[nn];
                float gf = gv.y + sBias[nn + 1];
                float gg = gv.z + sBias[nn + 2];
                float go = gv.w + sBias[nn + 3];
                float ct = fsigm(gf) * cS[i] + fsigm(gi) * ftanh(gg);
                cS[i] = ct;
                hout[(size_t)(m0 + m) * H2 + dir * H + nt * 32 + uu] =
                    __float2half(fsigm(go) * ftanh(ct));
            }
            barrier_grp(gid, 16);
            st0 = (st0 + 2) % 3;
        }

        // flush c for decoder re-tiling
        for (int i = tid; i < BM * 32; i += 256) {
            int m = i >> 5, uu = i & 31;
            g_c[(size_t)(m0 + m) * H2 + dir * H + nt * 32 + uu] = cS[i];
        }
        barrier_grp(12, NCTA);   // full transition barrier
    }

    // =============== decoder ===============
    {
        int mt = bx >> 5, nt = bx & 31;
        int gid = 8 + mt;                     // 4 groups of 32 CTAs
        int m0 = mt * BM, n0 = nt * BN;
        const __half* W = g_Wdec + (size_t)n0 * KDEC;

        // prologue: W-parts of chunks 0/1 (h-independent)
        load_B(dynu, W, KDEC, tid);
        CP_COMMIT();
        load_B(dynu + (uint32_t)STG_B, W + KC, KDEC, tid);
        CP_COMMIT();

        for (int i = tid; i < BM * 32; i += 256) {
            int m = i >> 5, uu = i & 31;
            cS[i] = ldcg(&g_c[(size_t)(m0 + m) * H2 + nt * 32 + uu]);
        }
        if (tid < BN) { sBias[tid] = g_bdec[n0 + tid]; sWin[tid] = g_win[n0 + tid]; }
        if (tid < 32) sFc[tid] = g_fcw[nt * 32 + tid];
        __syncthreads();

        int st0 = 0;
        for (int l = 0; l < L_OUT; l++) {
            int p = l & 1;
            const __half* hbase = g_h[p] + (size_t)m0 * H2;
            __half* hout = g_h[p ^ 1];

            load_A(dynu + (uint32_t)((st0 % 3) * STG_B), hbase, H2, tid, 1);
            CP_COMMIT();
            load_A(dynu + (uint32_t)(((st0 + 1) % 3) * STG_B), hbase + KC, H2, tid, 1);
            CP_COMMIT();

            // previous prediction partials (L1-bypass; barrier ordered)
            {
                int r = tid >> 2, q = tid & 3;
                float s = 0.0f;
                if (l > 0) {
                    const float* dp = g_dpart + (size_t)(l - 1) * 32 * B + m0 + r;
#pragma unroll
                    for (int j = 0; j < 8; j++) s += ldcg(dp + (q * 8 + j) * B);
                }
                predP[r][q] = s;
            }

            float acc[2][4][4];
#pragma unroll
            for (int a = 0; a < 2; a++)
#pragma unroll
                for (int bq = 0; bq < 4; bq++)
#pragma unroll
                    for (int cq = 0; cq < 4; cq++) acc[a][bq][cq] = 0.0f;

#pragma unroll
            for (int ch = 0; ch < NCHD; ch++) {
                CP_WAIT1();
                __syncthreads();
                int pf = ch + 2;
                if (pf <= 7) {
                    uint32_t su = dynu + (uint32_t)(((st0 + pf) % 3) * STG_B);
                    load_A(su, hbase + pf * KC, H2, tid, 1);
                    load_B(su, W + pf * KC, KDEC, tid);
                } else if (pf == 8 && l + 1 < L_OUT) {
                    load_B(dynu + (uint32_t)(((st0 + 2) % 3) * STG_B), W, KDEC, tid);
                } else if (pf == 9 && l + 1 < L_OUT) {
                    load_B(dynu + (uint32_t)((st0 % 3) * STG_B), W + KC, KDEC, tid);
                }
                CP_COMMIT();
                mma_chunk_lm(dynu + (uint32_t)(((st0 + ch) % 3) * STG_B), acc,
                             bA0, bA1, bB0, bB1);
            }

            if (tid < BM)
                predS[tid] = (l > 0)
                    ? (predP[tid][0] + predP[tid][1] + predP[tid][2] + predP[tid][3] + fcb0)
                    : 0.0f;
            store_gates(gS, acc, wm, wn, g, tg);
            __syncthreads();
            for (int i = tid; i < BM * 32; i += 256) {
                int m = i >> 5, uu = i & 31;
                float4 gv = *reinterpret_cast<const float4*>(gS + m * GSP + 4 * uu);
                int nn = 4 * uu;
                float pb = predS[m];
                float gi = gv.x + sBias[nn]     + pb * sWin[nn];
                float gf = gv.y + sBias[nn + 1] + pb * sWin[nn + 1];
                float gg = gv.z + sBias[nn + 2] + pb * sWin[nn + 2];
                float go = gv.w + sBias[nn + 3] + pb * sWin[nn + 3];
                float ct = fsigm(gf) * cS[i] + fsigm(gi) * ftanh(gg);
                cS[i] = ct;
                float ht = fsigm(go) * ftanh(ct);
                hout[(size_t)(m0 + m) * H2 + nt * 32 + uu] = __float2half(ht);
                Hs[m * HSP + uu] = ht;
            }
            __syncthreads();
            if (tid < BM) {
                float s = 0.0f;
#pragma unroll
                for (int j = 0; j < 32; j++) s += sFc[j] * Hs[tid * HSP + j];
                g_dpart[(size_t)(l * 32 + nt) * B + m0 + tid] = s;
            }
            barrier_grp(gid, 32);
            st0 = (st0 + 2) % 3;
        }
    }

    // =============== finalize (after full barrier) ===============
    barrier_grp(13, NCTA);
    {
        int idx = bx * 256 + tid;
        if (idx < B * L_OUT) {
            int b = idx / L_OUT, l = idx - b * L_OUT;
            float s = fcb0;
#pragma unroll
            for (int j = 0; j < 32; j++) s += ldcg(&g_dpart[(size_t)(l * 32 + j) * B + b]);
            out[idx] = s;
        }
    }
}

// ---------------- launch ----------------
extern "C" void kernel_launch(void* const* d_in, const int* in_sizes, int n_in,
                              void* d_out, int out_size) {
    const float* x      = (const float*)d_in[0];
    const float* eWih_f = (const float*)d_in[1];
    const float* eWhh_f = (const float*)d_in[2];
    const float* ebih_f = (const float*)d_in[3];
    const float* ebhh_f = (const float*)d_in[4];
    const float* eWih_b = (const float*)d_in[5];
    const float* eWhh_b = (const float*)d_in[6];
    const float* ebih_b = (const float*)d_in[7];
    const float* ebhh_b = (const float*)d_in[8];
    const float* dWih   = (const float*)d_in[9];
    const float* dWhh   = (const float*)d_in[10];
    const float* dbih   = (const float*)d_in[11];
    const float* dbhh   = (const float*)d_in[12];
    const float* fcW    = (const float*)d_in[13];
    const float* fcb    = (const float*)d_in[14];

    cudaFuncSetAttribute(persist, cudaFuncAttributeMaxDynamicSharedMemorySize, DYNB);

    prep_misc<<<(T * B * F_IN + 255) / 256, 256>>>(x);
    prep_w<<<(PREP_TOT + 255) / 256, 256>>>(eWih_f, eWhh_f, ebih_f, ebhh_f,
                                            eWih_b, eWhh_b, ebih_b, ebhh_b,
                                            dWih, dWhh, dbih, dbhh, fcW);
    persist<<<NCTA, 256, DYNB>>>((float*)d_out, fcb);
}

// round 15
// speedup vs baseline: 4.7371x; 1.0879x over previous
#include <cuda_runtime.h>
#include <cuda_fp16.h>
#include <cstdint>
#include <math.h>

// ---------------- problem constants ----------------
#define B      256
#define T      168
#define F_IN   128
#define H      512
#define H4     2048
#define KENC   640
#define H2     1024
#define NDEC   4096
#define KDEC   1024
#define L_OUT  48

// ---------------- tiling ----------------
#define BM     64
#define BN     128
#define KC     128
#define PADH   136                      // halves; 272B row stride -> ldmatrix conflict-free
#define GSP    132                      // gate buffer stride (floats)
#define HSP    33
#define ASTG   (BM * PADH * 2)          // 17408 B per encoder A stage
#define BSTG   (BN * PADH * 2)          // 34816 B per W chunk
#define WOFFE  (3 * ASTG)               // 52224: encoder resident-W region
#define STG_B  ((BM + BN) * PADH * 2)   // 52224 B combined decoder stage
#define BOFF   ((uint32_t)(BM * PADH * 2))  // B-half offset inside combined stage
#define GOFFD  (3 * STG_B)              // 156672: decoder gate buffer
#define HOFFD  (GOFFD + BM * GSP * 4)   // 190464: decoder Hs buffer
#define DYNB   (WOFFE + 5 * BSTG)       // 226304 B dynamic smem
#define NCTA   128

// ---------------- device scratch ----------------
__device__ __align__(16) __half g_xT[(size_t)T * B * F_IN];
__device__ __align__(16) __half g_Wenc[2][H4 * KENC];
__device__ __align__(16) float  g_benc[2][H4];
__device__ __align__(16) __half g_Wdec[(size_t)NDEC * KDEC];
__device__ __align__(16) float  g_bdec[NDEC];
__device__ __align__(16) float  g_win[NDEC];
__device__ __align__(16) float  g_fcw[H2];
__device__ __align__(16) __half g_h[2][B * H2];
__device__ __align__(16) float  g_c[B * H2];
__device__ __align__(16) float  g_dpart[L_OUT * 32 * B];

__device__ unsigned g_bcnt[16];
__device__ unsigned g_bgen[16];

// ---------------- helpers (proven exp-based activations) ----------------
__device__ __forceinline__ float fsigm(float x) { return __fdividef(1.0f, 1.0f + __expf(-x)); }
__device__ __forceinline__ float ftanh(float x) { return __fdividef(2.0f, 1.0f + __expf(-2.0f * x)) - 1.0f; }
__device__ __forceinline__ float ldcg(const float* p) {
    float v; asm volatile("ld.global.cg.f32 %0, [%1];" : "=f"(v) : "l"(p)); return v;
}

__device__ __forceinline__ void barrier_grp(int gidx, unsigned n) {
    __syncthreads();
    if (threadIdx.x == 0) {
        unsigned cur, old;
        asm volatile("ld.relaxed.gpu.global.u32 %0, [%1];" : "=r"(cur) : "l"(&g_bgen[gidx]));
        asm volatile("atom.acq_rel.gpu.global.add.u32 %0, [%1], 1;" : "=r"(old) : "l"(&g_bcnt[gidx]));
        if (old == n - 1u) {
            asm volatile("st.relaxed.gpu.global.u32 [%0], %1;" :: "l"(&g_bcnt[gidx]), "r"(0u));
            asm volatile("st.release.gpu.global.u32 [%0], %1;" :: "l"(&g_bgen[gidx]), "r"(cur + 1u));
        } else {
            unsigned v;
            do {
                asm volatile("ld.acquire.gpu.global.u32 %0, [%1];" : "=r"(v) : "l"(&g_bgen[gidx]));
            } while (v == cur);
        }
    }
    __syncthreads();
}

__device__ __forceinline__ void cpa16_ca(uint32_t dst, const __half* src) {
    asm volatile("cp.async.ca.shared.global [%0], [%1], 16;\n" :: "r"(dst), "l"(src));
}
__device__ __forceinline__ void cpa16_cg(uint32_t dst, const __half* src) {
    asm volatile("cp.async.cg.shared.global [%0], [%1], 16;\n" :: "r"(dst), "l"(src));
}
#define CP_COMMIT() asm volatile("cp.async.commit_group;\n" ::: "memory")
#define CP_WAIT1()  asm volatile("cp.async.wait_group 1;\n" ::: "memory")
#define CP_WAIT0()  asm volatile("cp.async.wait_group 0;\n" ::: "memory")

__device__ __forceinline__ void load_A(uint32_t su, const __half* __restrict__ a,
                                       int astride, int tid, int cg) {
#pragma unroll
    for (int i = tid; i < BM * 16; i += 256) {
        int r = i >> 4, v = i & 15;
        uint32_t d = su + (uint32_t)(r * PADH + v * 8) * 2u;
        const __half* s = a + (size_t)r * astride + v * 8;
        if (cg) cpa16_cg(d, s); else cpa16_ca(d, s);
    }
}
__device__ __forceinline__ void load_B(uint32_t su, const __half* __restrict__ b,
                                       int bstride, int tid) {
#pragma unroll
    for (int i = tid; i < BN * 16; i += 256) {
        int r = i >> 4, v = i & 15;
        cpa16_ca(su + (uint32_t)(r * PADH + v * 8) * 2u, b + (size_t)r * bstride + v * 8);
    }
}

// ---------------- ldmatrix + mma ----------------
__device__ __forceinline__ void lm4(uint32_t (&r)[4], uint32_t addr) {
    asm volatile("ldmatrix.sync.aligned.m8n8.x4.shared.b16 {%0,%1,%2,%3}, [%4];"
                 : "=r"(r[0]), "=r"(r[1]), "=r"(r[2]), "=r"(r[3]) : "r"(addr));
}
__device__ __forceinline__ void hmma(float (&d)[4], const uint32_t (&a)[4],
                                     uint32_t b0, uint32_t b1) {
    asm volatile("mma.sync.aligned.m16n8k16.row.col.f32.f16.f16.f32 "
                 "{%0,%1,%2,%3},{%4,%5,%6,%7},{%8,%9},{%0,%1,%2,%3};"
                 : "+f"(d[0]), "+f"(d[1]), "+f"(d[2]), "+f"(d[3])
                 : "r"(a[0]), "r"(a[1]), "r"(a[2]), "r"(a[3]), "r"(b0), "r"(b1));
}
// one KC=128 chunk; asu = A base, bsu = B base (regions may differ)
__device__ __forceinline__ void mma_chunk_lm(uint32_t asu, uint32_t bsu,
                                             float (&acc)[2][4][4],
                                             uint32_t bA0, uint32_t bA1,
                                             uint32_t bB0, uint32_t bB1) {
#pragma unroll
    for (int kb = 0; kb < 8; kb++) {
        uint32_t ko = (uint32_t)kb * 32u;
        uint32_t a0[4], a1[4], b0[4], b1[4];
        lm4(a0, asu + ko + bA0);
        lm4(a1, asu + ko + bA1);
        lm4(b0, bsu + ko + bB0);
        lm4(b1, bsu + ko + bB1);
        hmma(acc[0][0], a0, b0[0], b0[2]);
        hmma(acc[0][1], a0, b0[1], b0[3]);
        hmma(acc[0][2], a0, b1[0], b1[2]);
        hmma(acc[0][3], a0, b1[1], b1[3]);
        hmma(acc[1][0], a1, b0[0], b0[2]);
        hmma(acc[1][1], a1, b0[1], b0[3]);
        hmma(acc[1][2], a1, b1[0], b1[2]);
        hmma(acc[1][3], a1, b1[1], b1[3]);
    }
}

__device__ __forceinline__ void store_gates(float* __restrict__ Gs,
                                            float (&acc)[2][4][4],
                                            int wm, int wn, int g, int tg) {
#pragma unroll
    for (int mi = 0; mi < 2; mi++)
#pragma unroll
        for (int ni = 0; ni < 4; ni++) {
            int row = wm * 32 + mi * 16 + g;
            int col = wn * 32 + ni * 8 + 2 * tg;
            Gs[row * GSP + col]           = acc[mi][ni][0];
            Gs[row * GSP + col + 1]       = acc[mi][ni][1];
            Gs[(row + 8) * GSP + col]     = acc[mi][ni][2];
            Gs[(row + 8) * GSP + col + 1] = acc[mi][ni][3];
        }
}

// ---------------- prep ----------------
__global__ void prep_misc(const float* __restrict__ x) {
    int i = blockIdx.x * blockDim.x + threadIdx.x;
    if (i < T * B * F_IN) {
        int f = i & 127;
        int r = i >> 7;
        int b = r & 255;
        int t = r >> 8;
        g_xT[i] = __float2half(x[((size_t)b * T + t) * F_IN + f]);
    }
    if (i < B * H2) {
        g_h[0][i] = __half(0.0f);
        g_h[1][i] = __half(0.0f);
        g_c[i]    = 0.0f;
    }
}

#define EW (2 * H4 * KENC)
#define DW (NDEC * KDEC)
#define PREP_TOT (EW + DW + 2 * H4 + NDEC + H2)

__global__ void prep_w(const float* __restrict__ eWih_f, const float* __restrict__ eWhh_f,
                       const float* __restrict__ ebih_f, const float* __restrict__ ebhh_f,
                       const float* __restrict__ eWih_b, const float* __restrict__ eWhh_b,
                       const float* __restrict__ ebih_b, const float* __restrict__ ebhh_b,
                       const float* __restrict__ dWih,   const float* __restrict__ dWhh,
                       const float* __restrict__ dbih,   const float* __restrict__ dbhh,
                       const float* __restrict__ fcW) {
    int i = blockIdx.x * blockDim.x + threadIdx.x;
    if (i >= PREP_TOT) return;

    if (i < EW) {
        int dir = i / (H4 * KENC);
        int r   = i - dir * (H4 * KENC);
        int n   = r / KENC;
        int k   = r - n * KENC;
        int u = n >> 2, gt = n & 3;
        int row = gt * H + u;
        const float* Wih = dir ? eWih_b : eWih_f;
        const float* Whh = dir ? eWhh_b : eWhh_f;
        float v = (k < F_IN) ? Wih[row * F_IN + k] : Whh[row * H + (k - F_IN)];
        g_Wenc[dir][n * KENC + k] = __float2half(v);
    } else if (i < EW + DW) {
        int r = i - EW;
        int n = r / KDEC;
        int k = r - n * KDEC;
        int u = n >> 2, gt = n & 3;
        int row = gt * H2 + u;
        g_Wdec[(size_t)n * KDEC + k] = __float2half(dWhh[(size_t)row * KDEC + k]);
    } else {
        int r = i - EW - DW;
        if (r < 2 * H4) {
            int dir = r >> 11;
            int n = r & (H4 - 1);
            int u = n >> 2, gt = n & 3;
            int row = gt * H + u;
            g_benc[dir][n] = dir ? (ebih_b[row] + ebhh_b[row]) : (ebih_f[row] + ebhh_f[row]);
        } else if (r < 2 * H4 + NDEC) {
            int n = r - 2 * H4;
            int u = n >> 2, gt = n & 3;
            int row = gt * H2 + u;
            g_bdec[n] = dbih[row] + dbhh[row];
            g_win[n]  = dWih[row];
        } else {
            int u = r - 2 * H4 - NDEC;
            g_fcw[u] = fcW[u];
        }
    }
}

// ---------------- persistent kernel ----------------
__global__ __launch_bounds__(256, 1) void persist(float* __restrict__ out,
                                                  const float* __restrict__ fcb) {
    extern __shared__ __align__(16) unsigned char dynraw[];
    float* gSe = reinterpret_cast<float*>(dynraw + ASTG);    // enc gates: overlays A stages 1-2
    float* gSd = reinterpret_cast<float*>(dynraw + GOFFD);   // dec gates
    float* Hs  = reinterpret_cast<float*>(dynraw + HOFFD);   // dec h staging
    __shared__ float sBias[BN];
    __shared__ float sWin[BN];
    __shared__ float sFc[32];
    __shared__ float predS[BM];
    __shared__ float predP[BM][4];

    uint32_t dynu = (uint32_t)__cvta_generic_to_shared(dynraw);
    int bx = blockIdx.x;
    int tid = threadIdx.x;
    int lane = tid & 31, wid = tid >> 5;
    int wm = wid & 1, wn = wid >> 1;
    int lg = lane >> 2, tg = lane & 3;
    int la15 = lane & 15, lk = (lane >> 4) << 3;
    float fcb0 = fcb[0];

    uint32_t bA0 = (uint32_t)((wm * 32 + la15) * PADH + lk) * 2u;
    uint32_t bA1 = bA0 + 16u * PADH * 2u;
    uint32_t bB0 = (uint32_t)((wn * 32 + la15) * PADH + lk) * 2u;
    uint32_t bB1 = bB0 + 16u * PADH * 2u;

    // =============== encoder (resident W, uniform one-commit-per-slot) ===============
    {
        int dir = bx >> 6;
        int mt  = (bx >> 4) & 3;
        int nt  = bx & 15;
        int gid = bx >> 4;                 // 8 groups of 16 CTAs sharing (dir, mt)
        int m0 = mt * BM, n0 = nt * BN;
        const __half* W = g_Wenc[dir] + (size_t)n0 * KENC;

        if (tid < BN) sBias[tid] = g_benc[dir][n0 + tid];

        // prologue: resident W chunks (5 groups), then X(0) (1 group)
#pragma unroll
        for (int c = 0; c < 5; c++) {
            load_B(dynu + (uint32_t)(WOFFE + c * BSTG), W + c * KC, KENC, tid);
            CP_COMMIT();
        }
        {
            int tt0 = dir ? (T - 1) : 0;
            load_A(dynu, g_xT + ((size_t)tt0 * B + m0) * F_IN, F_IN, tid, 0);
            CP_COMMIT();
        }

        for (int t = 0; t < T; t++) {
            int p = t & 1;
            const __half* hb = g_h[p] + (size_t)m0 * H2 + dir * H;
            __half* hout = g_h[p ^ 1];

            load_A(dynu + 1u * ASTG, hb, H2, tid, 1);   // A1 (h cols 0-127)
            CP_COMMIT();

            float acc[2][4][4];
#pragma unroll
            for (int a = 0; a < 2; a++)
#pragma unroll
                for (int bq = 0; bq < 4; bq++)
#pragma unroll
                    for (int cq = 0; cq < 4; cq++) acc[a][bq][cq] = 0.0f;

#pragma unroll
            for (int ch = 0; ch < 5; ch++) {
                if (ch == 4) { CP_WAIT0(); } else { CP_WAIT1(); }
                __syncthreads();
                if (ch == 0) {
                    load_A(dynu + 2u * ASTG, hb + 128, H2, tid, 1);   // A2 -> st2
                } else if (ch == 1) {
                    load_A(dynu + 0u * ASTG, hb + 256, H2, tid, 1);   // A3 -> st0
                } else if (ch == 2) {
                    load_A(dynu + 1u * ASTG, hb + 384, H2, tid, 1);   // A4 -> st1
                } else if (ch == 4 && t + 1 < T) {
                    int tt2 = dir ? (T - 2 - t) : (t + 1);
                    load_A(dynu, g_xT + ((size_t)tt2 * B + m0) * F_IN, F_IN, tid, 0); // X(t+1) -> st0
                }
                CP_COMMIT();   // uniform: one group per slot (empty allowed)
                mma_chunk_lm(dynu + (uint32_t)((ch % 3) * ASTG),
                             dynu + (uint32_t)(WOFFE + ch * BSTG),
                             acc, bA0, bA1, bB0, bB1);
            }

            __syncthreads();                 // protect stage-1 reads before gSe overwrite
            store_gates(gSe, acc, wm, wn, lg, tg);
            __syncthreads();
            for (int i = tid; i < BM * 32; i += 256) {
                int m = i >> 5, uu = i & 31;
                float4 gv = *reinterpret_cast<const float4*>(gSe + m * GSP + 4 * uu);
                int nn = 4 * uu;
                float gi = gv.x + sBias[nn];
                float gf = gv.y + sBias[nn + 1];
                float gg = gv.z + sBias[nn + 2];
                float go = gv.w + sBias[nn + 3];
                int cidx = (m0 + m) * H2 + dir * H + nt * 32 + uu;
                float c = ldcg(&g_c[cidx]);
                float ct = fsigm(gf) * c + fsigm(gi) * ftanh(gg);
                g_c[cidx] = ct;
                hout[(size_t)(m0 + m) * H2 + dir * H + nt * 32 + uu] =
                    __float2half(fsigm(go) * ftanh(ct));
            }
            barrier_grp(gid, 16);
        }
        barrier_grp(12, NCTA);   // full transition barrier
    }

    // =============== decoder (proven R10 combined-stage schedule) ===============
    {
        int mt = bx >> 5, nt = bx & 31;
        int gid = 8 + mt;                  // 4 groups of 32 CTAs
        int m0 = mt * BM, n0 = nt * BN;
        const __half* W = g_Wdec + (size_t)n0 * KDEC;

        // prologue: W-parts of chunks 0/1 (h-independent)
        load_B(dynu + BOFF, W, KDEC, tid);
        CP_COMMIT();
        load_B(dynu + (uint32_t)STG_B + BOFF, W + KC, KDEC, tid);
        CP_COMMIT();

        if (tid < BN) { sBias[tid] = g_bdec[n0 + tid]; sWin[tid] = g_win[n0 + tid]; }
        if (tid < 32) sFc[tid] = g_fcw[nt * 32 + tid];
        __syncthreads();

        int st0 = 0;
        for (int l = 0; l < L_OUT; l++) {
            int p = l & 1;
            const __half* hbase = g_h[p] + (size_t)m0 * H2;
            __half* hout = g_h[p ^ 1];

            load_A(dynu + (uint32_t)((st0 % 3) * STG_B), hbase, H2, tid, 1);
            CP_COMMIT();
            load_A(dynu + (uint32_t)(((st0 + 1) % 3) * STG_B), hbase + KC, H2, tid, 1);
            CP_COMMIT();

            // previous prediction partials (L1-bypass; barrier ordered)
            {
                int r = tid >> 2, q = tid & 3;
                float s = 0.0f;
                if (l > 0) {
                    const float* dp = g_dpart + (size_t)(l - 1) * 32 * B + m0 + r;
#pragma unroll
                    for (int j = 0; j < 8; j++) s += ldcg(dp + (q * 8 + j) * B);
                }
                predP[r][q] = s;
            }

            float acc[2][4][4];
#pragma unroll
            for (int a = 0; a < 2; a++)
#pragma unroll
                for (int bq = 0; bq < 4; bq++)
#pragma unroll
                    for (int cq = 0; cq < 4; cq++) acc[a][bq][cq] = 0.0f;

#pragma unroll
            for (int ch = 0; ch < 8; ch++) {
                if (ch == 7 && l + 1 >= L_OUT) { CP_WAIT0(); } else { CP_WAIT1(); }
                __syncthreads();
                int pf = ch + 2;
                if (pf <= 7) {
                    uint32_t su = dynu + (uint32_t)(((st0 + pf) % 3) * STG_B);
                    load_A(su, hbase + pf * KC, H2, tid, 1);
                    load_B(su + BOFF, W + pf * KC, KDEC, tid);
                } else if (pf == 8 && l + 1 < L_OUT) {
                    load_B(dynu + (uint32_t)(((st0 + 2) % 3) * STG_B) + BOFF, W, KDEC, tid);
                } else if (pf == 9 && l + 1 < L_OUT) {
                    load_B(dynu + (uint32_t)((st0 % 3) * STG_B) + BOFF, W + KC, KDEC, tid);
                }
                CP_COMMIT();
                uint32_t su2 = dynu + (uint32_t)(((st0 + ch) % 3) * STG_B);
                mma_chunk_lm(su2, su2 + BOFF, acc, bA0, bA1, bB0, bB1);
            }
            __syncthreads();

            if (tid < BM)
                predS[tid] = (l > 0)
                    ? (predP[tid][0] + predP[tid][1] + predP[tid][2] + predP[tid][3] + fcb0)
                    : 0.0f;
            store_gates(gSd, acc, wm, wn, lg, tg);
            __syncthreads();
            for (int i = tid; i < BM * 32; i += 256) {
                int m = i >> 5, uu = i & 31;
                float4 gv = *reinterpret_cast<const float4*>(gSd + m * GSP + 4 * uu);
                int nn = 4 * uu;
                float pb = predS[m];
                float gi = gv.x + sBias[nn]     + pb * sWin[nn];
                float gf = gv.y + sBias[nn + 1] + pb * sWin[nn + 1];
                float gg = gv.z + sBias[nn + 2] + pb * sWin[nn + 2];
                float go = gv.w + sBias[nn + 3] + pb * sWin[nn + 3];
                int cidx = (m0 + m) * H2 + nt * 32 + uu;
                float c = ldcg(&g_c[cidx]);
                float ct = fsigm(gf) * c + fsigm(gi) * ftanh(gg);
                g_c[cidx] = ct;
                float ht = fsigm(go) * ftanh(ct);
                hout[(size_t)(m0 + m) * H2 + nt * 32 + uu] = __float2half(ht);
                Hs[m * HSP + uu] = ht;
            }
            __syncthreads();
            if (tid < BM) {
                float s = 0.0f;
#pragma unroll
                for (int j = 0; j < 32; j++) s += sFc[j] * Hs[tid * HSP + j];
                g_dpart[(size_t)(l * 32 + nt) * B + m0 + tid] = s;
            }
            barrier_grp(gid, 32);
            st0 = (st0 + 2) % 3;
        }
    }

    // =============== finalize ===============
    barrier_grp(13, NCTA);
    {
        int idx = bx * 256 + tid;
        if (idx < B * L_OUT) {
            int b = idx / L_OUT, l = idx - b * L_OUT;
            float s = fcb0;
#pragma unroll
            for (int j = 0; j < 32; j++) s += ldcg(&g_dpart[(size_t)(l * 32 + j) * B + b]);
            out[idx] = s;
        }
    }
}

// ---------------- launch ----------------
extern "C" void kernel_launch(void* const* d_in, const int* in_sizes, int n_in,
                              void* d_out, int out_size) {
    const float* x      = (const float*)d_in[0];
    const float* eWih_f = (const float*)d_in[1];
    const float* eWhh_f = (const float*)d_in[2];
    const float* ebih_f = (const float*)d_in[3];
    const float* ebhh_f = (const float*)d_in[4];
    const float* eWih_b = (const float*)d_in[5];
    const float* eWhh_b = (const float*)d_in[6];
    const float* ebih_b = (const float*)d_in[7];
    const float* ebhh_b = (const float*)d_in[8];
    const float* dWih   = (const float*)d_in[9];
    const float* dWhh   = (const float*)d_in[10];
    const float* dbih   = (const float*)d_in[11];
    const float* dbhh   = (const float*)d_in[12];
    const float* fcW    = (const float*)d_in[13];
    const float* fcb    = (const float*)d_in[14];

    cudaFuncSetAttribute(persist, cudaFuncAttributeMaxDynamicSharedMemorySize, DYNB);

    prep_misc<<<(T * B * F_IN + 255) / 256, 256>>>(x);
    prep_w<<<(PREP_TOT + 255) / 256, 256>>>(eWih_f, eWhh_f, ebih_f, ebhh_f,
                                            eWih_b, eWhh_b, ebih_b, ebhh_b,
                                            dWih, dWhh, dbih, dbhh, fcW);
    persist<<<NCTA, 256, DYNB>>>((float*)d_out, fcb);
}